// round 1
// baseline (speedup 1.0000x reference)
#include <cuda_runtime.h>
#include <cuda_bf16.h>
#include <cstddef>

// Problem constants
#define SEQ   2048
#define BATCH 2
#define TOK   (SEQ * BATCH)   // 4096
#define DM    2048
#define NH    32
#define NKV   8
#define HD    64
#define KVD   (NKV * HD)      // 512

// ------------------------------------------------------------------
// Scratch (device globals; no cudaMalloc allowed)
// ------------------------------------------------------------------
__device__ float g_q[(size_t)TOK * DM];     // Q after proj (+RoPE), [T, H*64]
__device__ float g_k[(size_t)TOK * KVD];    // K after proj (+RoPE), [T, KV*64]
__device__ float g_v[(size_t)TOK * KVD];    // V, [T, KV*64]
__device__ float g_attn[(size_t)TOK * DM];  // attention output, [T, H*64]

// Exact fp32 rounding of 10000^(-i/32), i = 0..31
__device__ __constant__ float c_invfreq[32] = {
    1.0f, 0.7498942093324559f, 0.5623413251903491f, 0.4216965034285822f,
    0.31622776601683794f, 0.23713737056616552f, 0.17782794100389228f, 0.1333521432163324f,
    0.1f, 0.07498942093324559f, 0.05623413251903491f, 0.04216965034285822f,
    0.031622776601683794f, 0.023713737056616552f, 0.017782794100389228f, 0.01333521432163324f,
    0.01f, 0.007498942093324559f, 0.005623413251903491f, 0.004216965034285822f,
    0.0031622776601683794f, 0.0023713737056616552f, 0.0017782794100389228f, 0.001333521432163324f,
    0.001f, 0.0007498942093324559f, 0.0005623413251903491f, 0.0004216965034285822f,
    0.00031622776601683794f, 0.00023713737056616552f, 0.00017782794100389228f, 0.0001333521432163324f
};

// ------------------------------------------------------------------
// SGEMM: C[M,N] = A[M,K] @ B[K,N], all row-major fp32.
// 128x128 block tile, K-tile 8, 256 threads, 8x8 per-thread micro-tile,
// 1-deep register prefetch of the next global tile.
// Requires M%128==0, N%128==0, K%8==0 (true for all calls here).
// ------------------------------------------------------------------
__global__ __launch_bounds__(256, 2)
void sgemm_kernel(const float* __restrict__ A, const float* __restrict__ B,
                  float* __restrict__ C, int M, int N, int K)
{
    __shared__ float As[8][132];   // transposed A tile, padded
    __shared__ float Bs[8][128];

    const int tid = threadIdx.x;
    const int tx = tid & 15, ty = tid >> 4;
    const int m0 = blockIdx.y * 128, n0 = blockIdx.x * 128;

    const int arow = tid >> 1, acol = (tid & 1) << 2;   // A: 128 rows x 8 cols
    const int brow = tid >> 5, bcol = (tid & 31) << 2;  // B: 8 rows x 128 cols

    const float* Ap = A + (size_t)(m0 + arow) * K + acol;
    const float* Bp = B + (size_t)brow * N + n0 + bcol;

    float acc[8][8];
#pragma unroll
    for (int i = 0; i < 8; i++)
#pragma unroll
        for (int j = 0; j < 8; j++) acc[i][j] = 0.0f;

    float4 a4 = *(const float4*)(Ap);
    float4 b4 = *(const float4*)(Bp);

    for (int k0 = 0; k0 < K; k0 += 8) {
        As[acol + 0][arow] = a4.x;
        As[acol + 1][arow] = a4.y;
        As[acol + 2][arow] = a4.z;
        As[acol + 3][arow] = a4.w;
        *(float4*)&Bs[brow][bcol] = b4;
        __syncthreads();

        if (k0 + 8 < K) {
            a4 = *(const float4*)(Ap + k0 + 8);
            b4 = *(const float4*)(Bp + (size_t)(k0 + 8) * N);
        }

#pragma unroll
        for (int kk = 0; kk < 8; kk++) {
            float af[8], bf[8];
            *(float4*)&af[0] = *(const float4*)&As[kk][ty * 8];
            *(float4*)&af[4] = *(const float4*)&As[kk][ty * 8 + 4];
            *(float4*)&bf[0] = *(const float4*)&Bs[kk][tx * 8];
            *(float4*)&bf[4] = *(const float4*)&Bs[kk][tx * 8 + 4];
#pragma unroll
            for (int i = 0; i < 8; i++)
#pragma unroll
                for (int j = 0; j < 8; j++)
                    acc[i][j] = fmaf(af[i], bf[j], acc[i][j]);
        }
        __syncthreads();
    }

#pragma unroll
    for (int i = 0; i < 8; i++) {
        float* Cp = C + (size_t)(m0 + ty * 8 + i) * N + n0 + tx * 8;
        *(float4*)Cp       = make_float4(acc[i][0], acc[i][1], acc[i][2], acc[i][3]);
        *(float4*)(Cp + 4) = make_float4(acc[i][4], acc[i][5], acc[i][6], acc[i][7]);
    }
}

// ------------------------------------------------------------------
// RoPE (interleaved pairs), in-place on g_q and g_k.
// ------------------------------------------------------------------
__global__ void rope_kernel(float* __restrict__ Qb, float* __restrict__ Kb,
                            const int* __restrict__ pos_ids)
{
    const int PAIRS_PER_TOK = (DM / 2) + (KVD / 2); // 1024 + 256 = 1280
    int idx = blockIdx.x * blockDim.x + threadIdx.x;
    int total = TOK * PAIRS_PER_TOK;
    if (idx >= total) return;

    int t = idx / PAIRS_PER_TOK;
    int p = idx - t * PAIRS_PER_TOK;

    float* base;
    int i;
    if (p < DM / 2) {
        int head = p >> 5;            // 32 pairs per head
        i = p & 31;
        base = Qb + (size_t)t * DM + head * HD + 2 * i;
    } else {
        int pk = p - DM / 2;
        int head = pk >> 5;
        i = pk & 31;
        base = Kb + (size_t)t * KVD + head * HD + 2 * i;
    }

    float pos = (float)pos_ids[t];
    float ang = pos * c_invfreq[i];
    float s, c;
    sincosf(ang, &s, &c);
    float x0 = base[0], x1 = base[1];
    base[0] = fmaf(x0, c, -x1 * s);
    base[1] = fmaf(x0, s,  x1 * c);
}

// ------------------------------------------------------------------
// Flash attention, fp32, causal + attention_mask, GQA (H=32 -> KV=8).
// Block = (q-tile of 64) x (head) x (batch). 256 threads (16x16),
// each thread owns a 4x4 S micro-tile and 4x4 O micro-tile.
// Q and K stored d-major (transposed) in smem for conflict-free reads.
// ------------------------------------------------------------------
#define FA_SMEM_FLOATS (64*65 + 64*68 + 64*64 + 64*65 + 64*16 + 4*64)
#define FA_SMEM_BYTES  (FA_SMEM_FLOATS * 4)

__global__ __launch_bounds__(256)
void flash_attn_kernel(const float* __restrict__ Q, const float* __restrict__ K,
                       const float* __restrict__ V, const int* __restrict__ mask,
                       float* __restrict__ Oout)
{
    extern __shared__ float sm[];
    float* Qts = sm;                  // [64 d][65]  (col = q row)
    float* Kts = Qts + 64 * 65;      // [64 d][68]  (col = k row)
    float* Vs  = Kts + 64 * 68;      // [64 k][64 d]
    float* Pts = Vs  + 64 * 64;      // [64 k][65]  (col = q row)
    float* red = Pts + 64 * 65;      // [64][16]
    float* m_s = red + 64 * 16;      // [64]
    float* l_s = m_s + 64;           // [64]
    float* al_s = l_s + 64;          // [64]
    float* kval = al_s + 64;         // [64]

    const int tid = threadIdx.x;
    const int tx = tid & 15, ty = tid >> 4;
    const int qt = blockIdx.x, h = blockIdx.y, b = blockIdx.z;
    const int q0 = qt * 64;
    const int kvh = h >> 2;          // GQA group size 4
    const float scale = 0.125f;      // 1/sqrt(64)

    // Load Q tile transposed (d-major)
#pragma unroll
    for (int it = 0; it < 4; it++) {
        int idx = tid + it * 256;
        int r = idx >> 4, d4 = (idx & 15) * 4;
        float4 v = *(const float4*)(Q + (size_t)(b * SEQ + q0 + r) * DM + h * HD + d4);
        Qts[(d4 + 0) * 65 + r] = v.x;
        Qts[(d4 + 1) * 65 + r] = v.y;
        Qts[(d4 + 2) * 65 + r] = v.z;
        Qts[(d4 + 3) * 65 + r] = v.w;
    }
    if (tid < 64) { m_s[tid] = -1e30f; l_s[tid] = 0.0f; }

    float o[4][4] = {{0.f,0.f,0.f,0.f},{0.f,0.f,0.f,0.f},{0.f,0.f,0.f,0.f},{0.f,0.f,0.f,0.f}};

    for (int kt = 0; kt <= qt; kt++) {
        const int k0 = kt * 64;
        __syncthreads();  // previous iteration done with Kts/Vs/Pts

        // Load K (transposed, d-major) and V (row-major)
#pragma unroll
        for (int it = 0; it < 4; it++) {
            int idx = tid + it * 256;
            int c = idx >> 4, d4 = (idx & 15) * 4;
            const size_t row = (size_t)(b * SEQ + k0 + c) * KVD + kvh * HD + d4;
            float4 kk = *(const float4*)(K + row);
            Kts[(d4 + 0) * 68 + c] = kk.x;
            Kts[(d4 + 1) * 68 + c] = kk.y;
            Kts[(d4 + 2) * 68 + c] = kk.z;
            Kts[(d4 + 3) * 68 + c] = kk.w;
            float4 vv = *(const float4*)(V + row);
            *(float4*)&Vs[c * 64 + d4] = vv;
        }
        if (tid < 64) kval[tid] = (mask[b * SEQ + k0 + tid] > 0) ? 1.0f : 0.0f;
        __syncthreads();

        // S = Q K^T (4x4 micro-tile per thread)
        float s[4][4] = {{0.f,0.f,0.f,0.f},{0.f,0.f,0.f,0.f},{0.f,0.f,0.f,0.f},{0.f,0.f,0.f,0.f}};
#pragma unroll 8
        for (int d = 0; d < 64; d++) {
            float a0 = Qts[d * 65 + ty * 4 + 0];
            float a1 = Qts[d * 65 + ty * 4 + 1];
            float a2 = Qts[d * 65 + ty * 4 + 2];
            float a3 = Qts[d * 65 + ty * 4 + 3];
            float4 bq = *(const float4*)&Kts[d * 68 + tx * 4];
            s[0][0] = fmaf(a0, bq.x, s[0][0]); s[0][1] = fmaf(a0, bq.y, s[0][1]);
            s[0][2] = fmaf(a0, bq.z, s[0][2]); s[0][3] = fmaf(a0, bq.w, s[0][3]);
            s[1][0] = fmaf(a1, bq.x, s[1][0]); s[1][1] = fmaf(a1, bq.y, s[1][1]);
            s[1][2] = fmaf(a1, bq.z, s[1][2]); s[1][3] = fmaf(a1, bq.w, s[1][3]);
            s[2][0] = fmaf(a2, bq.x, s[2][0]); s[2][1] = fmaf(a2, bq.y, s[2][1]);
            s[2][2] = fmaf(a2, bq.z, s[2][2]); s[2][3] = fmaf(a2, bq.w, s[2][3]);
            s[3][0] = fmaf(a3, bq.x, s[3][0]); s[3][1] = fmaf(a3, bq.y, s[3][1]);
            s[3][2] = fmaf(a3, bq.z, s[3][2]); s[3][3] = fmaf(a3, bq.w, s[3][3]);
        }

        // scale + causal + mask, per-row tile max
#pragma unroll
        for (int i = 0; i < 4; i++) {
            int gq = q0 + ty * 4 + i;
            float mx = -1e30f;
#pragma unroll
            for (int j = 0; j < 4; j++) {
                int gk = k0 + tx * 4 + j;
                bool ok = (gk <= gq) && (kval[tx * 4 + j] > 0.5f);
                s[i][j] = ok ? s[i][j] * scale : -1e30f;
                mx = fmaxf(mx, s[i][j]);
            }
            red[(ty * 4 + i) * 16 + tx] = mx;
        }
        __syncthreads();

        if (tid < 64) {
            float mx = red[tid * 16];
#pragma unroll
            for (int t2 = 1; t2 < 16; t2++) mx = fmaxf(mx, red[tid * 16 + t2]);
            float m_old = m_s[tid];
            float m_new = fmaxf(m_old, mx);
            al_s[tid] = expf(m_old - m_new);
            m_s[tid] = m_new;
        }
        __syncthreads();

        // P = exp(S - m), store transposed, partial row sums
        float rs[4];
#pragma unroll
        for (int i = 0; i < 4; i++) {
            float mrow = m_s[ty * 4 + i];
            float acc = 0.0f;
#pragma unroll
            for (int j = 0; j < 4; j++) {
                float p = expf(s[i][j] - mrow);
                Pts[(tx * 4 + j) * 65 + (ty * 4 + i)] = p;
                acc += p;
            }
            rs[i] = acc;
        }
#pragma unroll
        for (int i = 0; i < 4; i++) red[(ty * 4 + i) * 16 + tx] = rs[i];
        __syncthreads();

        if (tid < 64) {
            float sum = 0.0f;
#pragma unroll
            for (int t2 = 0; t2 < 16; t2++) sum += red[tid * 16 + t2];
            l_s[tid] = al_s[tid] * l_s[tid] + sum;
        }
        __syncthreads();

        // Rescale O and accumulate P @ V
        float al[4];
#pragma unroll
        for (int i = 0; i < 4; i++) al[i] = al_s[ty * 4 + i];
#pragma unroll
        for (int i = 0; i < 4; i++)
#pragma unroll
            for (int j = 0; j < 4; j++) o[i][j] *= al[i];

#pragma unroll 8
        for (int c = 0; c < 64; c++) {
            float a0 = Pts[c * 65 + ty * 4 + 0];
            float a1 = Pts[c * 65 + ty * 4 + 1];
            float a2 = Pts[c * 65 + ty * 4 + 2];
            float a3 = Pts[c * 65 + ty * 4 + 3];
            float4 bv = *(const float4*)&Vs[c * 64 + tx * 4];
            o[0][0] = fmaf(a0, bv.x, o[0][0]); o[0][1] = fmaf(a0, bv.y, o[0][1]);
            o[0][2] = fmaf(a0, bv.z, o[0][2]); o[0][3] = fmaf(a0, bv.w, o[0][3]);
            o[1][0] = fmaf(a1, bv.x, o[1][0]); o[1][1] = fmaf(a1, bv.y, o[1][1]);
            o[1][2] = fmaf(a1, bv.z, o[1][2]); o[1][3] = fmaf(a1, bv.w, o[1][3]);
            o[2][0] = fmaf(a2, bv.x, o[2][0]); o[2][1] = fmaf(a2, bv.y, o[2][1]);
            o[2][2] = fmaf(a2, bv.z, o[2][2]); o[2][3] = fmaf(a2, bv.w, o[2][3]);
            o[3][0] = fmaf(a3, bv.x, o[3][0]); o[3][1] = fmaf(a3, bv.y, o[3][1]);
            o[3][2] = fmaf(a3, bv.z, o[3][2]); o[3][3] = fmaf(a3, bv.w, o[3][3]);
        }
    }

    // Normalize and write out [T, H*64]
#pragma unroll
    for (int i = 0; i < 4; i++) {
        float inv = 1.0f / l_s[ty * 4 + i];
        float4 w = make_float4(o[i][0] * inv, o[i][1] * inv, o[i][2] * inv, o[i][3] * inv);
        *(float4*)(Oout + (size_t)(b * SEQ + q0 + ty * 4 + i) * DM + h * HD + tx * 4) = w;
    }
}

// ------------------------------------------------------------------
// Launch
// ------------------------------------------------------------------
extern "C" void kernel_launch(void* const* d_in, const int* in_sizes, int n_in,
                              void* d_out, int out_size)
{
    (void)in_sizes; (void)n_in; (void)out_size;
    const float* X    = (const float*)d_in[0];  // hidden_states [2,2048,2048]
    const int*   mask = (const int*)  d_in[1];  // attention_mask [2,2048]
    const int*   pos  = (const int*)  d_in[2];  // position_ids [2,2048]
    const float* Wq   = (const float*)d_in[3];  // [2048,2048]
    const float* Wk   = (const float*)d_in[4];  // [2048,512]
    const float* Wv   = (const float*)d_in[5];  // [2048,512]
    const float* Wo   = (const float*)d_in[6];  // [2048,2048]
    float* out = (float*)d_out;                 // [2,2048,2048]

    float *q, *k, *v, *attn;
    cudaGetSymbolAddress((void**)&q,    g_q);
    cudaGetSymbolAddress((void**)&k,    g_k);
    cudaGetSymbolAddress((void**)&v,    g_v);
    cudaGetSymbolAddress((void**)&attn, g_attn);

    // QKV projections
    sgemm_kernel<<<dim3(DM / 128, TOK / 128), 256>>>(X, Wq, q, TOK, DM, DM);
    sgemm_kernel<<<dim3(KVD / 128, TOK / 128), 256>>>(X, Wk, k, TOK, KVD, DM);
    sgemm_kernel<<<dim3(KVD / 128, TOK / 128), 256>>>(X, Wv, v, TOK, KVD, DM);

    // RoPE on Q and K
    {
        int total = TOK * ((DM / 2) + (KVD / 2));
        rope_kernel<<<(total + 255) / 256, 256>>>(q, k, pos);
    }

    // Flash attention
    cudaFuncSetAttribute(flash_attn_kernel,
                         cudaFuncAttributeMaxDynamicSharedMemorySize, FA_SMEM_BYTES);
    flash_attn_kernel<<<dim3(SEQ / 64, NH, BATCH), 256, FA_SMEM_BYTES>>>(q, k, v, mask, attn);

    // Output projection
    sgemm_kernel<<<dim3(DM / 128, TOK / 128), 256>>>(attn, Wo, out, TOK, DM, DM);
}

// round 3
// speedup vs baseline: 1.3822x; 1.3822x over previous
#include <cuda_runtime.h>
#include <cuda_bf16.h>
#include <cstdint>
#include <cstddef>

// Problem constants
#define SEQ   2048
#define BATCH 2
#define TOK   (SEQ * BATCH)   // 4096
#define DM    2048
#define NH    32
#define NKV   8
#define HD    64
#define KVD   (NKV * HD)      // 512

// ------------------------------------------------------------------
// Scratch (device globals; no cudaMalloc allowed)
// ------------------------------------------------------------------
__device__ float g_q[(size_t)TOK * DM];
__device__ float g_k[(size_t)TOK * KVD];
__device__ float g_v[(size_t)TOK * KVD];
__device__ float g_attn[(size_t)TOK * DM];

// Exact fp32 rounding of 10000^(-i/32), i = 0..31
__device__ __constant__ float c_invfreq[32] = {
    1.0f, 0.7498942093324559f, 0.5623413251903491f, 0.4216965034285822f,
    0.31622776601683794f, 0.23713737056616552f, 0.17782794100389228f, 0.1333521432163324f,
    0.1f, 0.07498942093324559f, 0.05623413251903491f, 0.04216965034285822f,
    0.031622776601683794f, 0.023713737056616552f, 0.017782794100389228f, 0.01333521432163324f,
    0.01f, 0.007498942093324559f, 0.005623413251903491f, 0.004216965034285822f,
    0.0031622776601683794f, 0.0023713737056616552f, 0.0017782794100389228f, 0.001333521432163324f,
    0.001f, 0.0007498942093324559f, 0.0005623413251903491f, 0.0004216965034285822f,
    0.00031622776601683794f, 0.00023713737056616552f, 0.00017782794100389228f, 0.0001333521432163324f
};

// ------------------------------------------------------------------
// tf32 helpers (baseline PTX, works on compute_103 virtual arch)
// ------------------------------------------------------------------
__device__ __forceinline__ uint32_t f2tf32(float x) {
    uint32_t r;
    asm("cvt.rna.tf32.f32 %0, %1;" : "=r"(r) : "f"(x));
    return r;
}
__device__ __forceinline__ void mma_tf32(float c[4], const uint32_t a[4], const uint32_t b[2]) {
    asm volatile("mma.sync.aligned.m16n8k8.row.col.f32.tf32.tf32.f32 "
                 "{%0,%1,%2,%3}, {%4,%5,%6,%7}, {%8,%9}, {%0,%1,%2,%3};"
                 : "+f"(c[0]), "+f"(c[1]), "+f"(c[2]), "+f"(c[3])
                 : "r"(a[0]), "r"(a[1]), "r"(a[2]), "r"(a[3]), "r"(b[0]), "r"(b[1]));
}

// ==================================================================
// tf32 mma.sync GEMM: C[M,N] = A[M,K] @ B[K,N], A,B,C row-major fp32.
// CTA tile 128x128, K-chunk 32, 512 threads (16 warps, warp tile 32x32),
// double-buffered smem + register prefetch.
// A smem: [128][36] (pad 36 -> frag bank = 4g+q, conflict-free)
// B smem: [32][136] (pad 136 -> frag bank = 8q+g, conflict-free)
// ==================================================================
#define GBM 128
#define GBN 128
#define GBK 32
#define AS_U32 (128 * 36)   // 4608 u32 = 18432 B
#define BS_U32 (32 * 136)   // 4352 u32 = 17408 B
#define GEMM_SMEM_BYTES ((AS_U32 + BS_U32) * 2 * 4)  // 71680

__global__ __launch_bounds__(512, 2)
void mma_gemm(const float* __restrict__ A, const float* __restrict__ B,
              float* __restrict__ C, int N, int K)
{
    extern __shared__ uint32_t smu[];
    uint32_t* As = smu;                    // 2 buffers of AS_U32
    uint32_t* Bs = smu + 2 * AS_U32;       // 2 buffers of BS_U32

    const int tid = threadIdx.x;
    const int wid = tid >> 5, lane = tid & 31;
    const int g = lane >> 2, q = lane & 3;
    const int warp_m = wid >> 2;           // 0..3
    const int warp_n = wid & 3;            // 0..3
    const int m0 = blockIdx.y * GBM, n0 = blockIdx.x * GBN;

    // global load addressing (per thread: 2 float4 of A, 2 float4 of B per chunk)
    const int arow = tid >> 3;             // 0..63
    const int acol4 = (tid & 7) * 4;       // k within chunk
    const int brow = tid >> 5;             // 0..15  (k within chunk)
    const int bcol4 = (tid & 31) * 4;      // n within tile
    const float* Ag = A + (size_t)(m0 + arow) * K + acol4;
    const float* Bg = B + (size_t)brow * N + n0 + bcol4;

    float acc[2][4][4];
#pragma unroll
    for (int mt = 0; mt < 2; mt++)
#pragma unroll
        for (int nt = 0; nt < 4; nt++)
#pragma unroll
            for (int e = 0; e < 4; e++) acc[mt][nt][e] = 0.0f;

    float4 pa[2], pb[2];

    // prologue: chunk 0
#pragma unroll
    for (int it = 0; it < 2; it++) {
        pa[it] = *(const float4*)(Ag + (size_t)it * 64 * K);
        pb[it] = *(const float4*)(Bg + (size_t)it * 16 * N);
    }
#pragma unroll
    for (int it = 0; it < 2; it++) {
        uint32_t* ap = As + (arow + it * 64) * 36 + acol4;
        ap[0] = f2tf32(pa[it].x); ap[1] = f2tf32(pa[it].y);
        ap[2] = f2tf32(pa[it].z); ap[3] = f2tf32(pa[it].w);
        uint32_t* bp = Bs + (brow + it * 16) * 136 + bcol4;
        bp[0] = f2tf32(pb[it].x); bp[1] = f2tf32(pb[it].y);
        bp[2] = f2tf32(pb[it].z); bp[3] = f2tf32(pb[it].w);
    }
    __syncthreads();

    const int nCh = K / GBK;
    for (int c = 0; c < nCh; c++) {
        const int b = c & 1;
        const uint32_t* as = As + b * AS_U32;
        const uint32_t* bs = Bs + b * BS_U32;

        if (c + 1 < nCh) {
            const int k0 = (c + 1) * GBK;
#pragma unroll
            for (int it = 0; it < 2; it++) {
                pa[it] = *(const float4*)(Ag + k0 + (size_t)it * 64 * K);
                pb[it] = *(const float4*)(Bg + (size_t)(k0 + it * 16) * N);
            }
        }

#pragma unroll
        for (int ks = 0; ks < 4; ks++) {
            uint32_t af[2][4], bf[4][2];
            const int kc = ks * 8 + q;
#pragma unroll
            for (int mt = 0; mt < 2; mt++) {
                const int r0 = warp_m * 32 + mt * 16 + g;
                af[mt][0] = as[r0 * 36 + kc];
                af[mt][1] = as[(r0 + 8) * 36 + kc];
                af[mt][2] = as[r0 * 36 + kc + 4];
                af[mt][3] = as[(r0 + 8) * 36 + kc + 4];
            }
#pragma unroll
            for (int nt = 0; nt < 4; nt++) {
                const int n = warp_n * 32 + nt * 8 + g;
                bf[nt][0] = bs[kc * 136 + n];
                bf[nt][1] = bs[(kc + 4) * 136 + n];
            }
#pragma unroll
            for (int mt = 0; mt < 2; mt++)
#pragma unroll
                for (int nt = 0; nt < 4; nt++)
                    mma_tf32(acc[mt][nt], af[mt], bf[nt]);
        }

        if (c + 1 < nCh) {
            uint32_t* aw = As + (1 - b) * AS_U32;
            uint32_t* bw = Bs + (1 - b) * BS_U32;
#pragma unroll
            for (int it = 0; it < 2; it++) {
                uint32_t* ap = aw + (arow + it * 64) * 36 + acol4;
                ap[0] = f2tf32(pa[it].x); ap[1] = f2tf32(pa[it].y);
                ap[2] = f2tf32(pa[it].z); ap[3] = f2tf32(pa[it].w);
                uint32_t* bp = bw + (brow + it * 16) * 136 + bcol4;
                bp[0] = f2tf32(pb[it].x); bp[1] = f2tf32(pb[it].y);
                bp[2] = f2tf32(pb[it].z); bp[3] = f2tf32(pb[it].w);
            }
        }
        __syncthreads();
    }

    // epilogue: c0 at (row g, col 2q), c1 (g, 2q+1), c2/c3 at row g+8
#pragma unroll
    for (int mt = 0; mt < 2; mt++) {
#pragma unroll
        for (int nt = 0; nt < 4; nt++) {
            const int row = m0 + warp_m * 32 + mt * 16 + g;
            const int col = n0 + warp_n * 32 + nt * 8 + q * 2;
            *(float2*)(C + (size_t)row * N + col) = make_float2(acc[mt][nt][0], acc[mt][nt][1]);
            *(float2*)(C + (size_t)(row + 8) * N + col) = make_float2(acc[mt][nt][2], acc[mt][nt][3]);
        }
    }
}

// ------------------------------------------------------------------
// RoPE (interleaved pairs), in-place on g_q and g_k.
// ------------------------------------------------------------------
__global__ void rope_kernel(float* __restrict__ Qb, float* __restrict__ Kb,
                            const int* __restrict__ pos_ids)
{
    const int PAIRS_PER_TOK = (DM / 2) + (KVD / 2); // 1280
    int idx = blockIdx.x * blockDim.x + threadIdx.x;
    int total = TOK * PAIRS_PER_TOK;
    if (idx >= total) return;

    int t = idx / PAIRS_PER_TOK;
    int p = idx - t * PAIRS_PER_TOK;

    float* base;
    int i;
    if (p < DM / 2) {
        int head = p >> 5;
        i = p & 31;
        base = Qb + (size_t)t * DM + head * HD + 2 * i;
    } else {
        int pk = p - DM / 2;
        int head = pk >> 5;
        i = pk & 31;
        base = Kb + (size_t)t * KVD + head * HD + 2 * i;
    }

    float pos = (float)pos_ids[t];
    float ang = pos * c_invfreq[i];
    float s, c;
    sincosf(ang, &s, &c);
    float x0 = base[0], x1 = base[1];
    base[0] = fmaf(x0, c, -x1 * s);
    base[1] = fmaf(x0, s,  x1 * c);
}

// ------------------------------------------------------------------
// Flash attention, fp32, causal + attention_mask, GQA (H=32 -> KV=8).
// (SIMT; tensorize next round)
// ------------------------------------------------------------------
#define FA_SMEM_FLOATS (64*65 + 64*68 + 64*64 + 64*65 + 64*16 + 4*64)
#define FA_SMEM_BYTES  (FA_SMEM_FLOATS * 4)

__global__ __launch_bounds__(256)
void flash_attn_kernel(const float* __restrict__ Q, const float* __restrict__ K,
                       const float* __restrict__ V, const int* __restrict__ mask,
                       float* __restrict__ Oout)
{
    extern __shared__ float sm[];
    float* Qts = sm;
    float* Kts = Qts + 64 * 65;
    float* Vs  = Kts + 64 * 68;
    float* Pts = Vs  + 64 * 64;
    float* red = Pts + 64 * 65;
    float* m_s = red + 64 * 16;
    float* l_s = m_s + 64;
    float* al_s = l_s + 64;
    float* kval = al_s + 64;

    const int tid = threadIdx.x;
    const int tx = tid & 15, ty = tid >> 4;
    const int qt = blockIdx.x, h = blockIdx.y, b = blockIdx.z;
    const int q0 = qt * 64;
    const int kvh = h >> 2;
    const float scale = 0.125f;

#pragma unroll
    for (int it = 0; it < 4; it++) {
        int idx = tid + it * 256;
        int r = idx >> 4, d4 = (idx & 15) * 4;
        float4 v = *(const float4*)(Q + (size_t)(b * SEQ + q0 + r) * DM + h * HD + d4);
        Qts[(d4 + 0) * 65 + r] = v.x;
        Qts[(d4 + 1) * 65 + r] = v.y;
        Qts[(d4 + 2) * 65 + r] = v.z;
        Qts[(d4 + 3) * 65 + r] = v.w;
    }
    if (tid < 64) { m_s[tid] = -1e30f; l_s[tid] = 0.0f; }

    float o[4][4] = {{0.f,0.f,0.f,0.f},{0.f,0.f,0.f,0.f},{0.f,0.f,0.f,0.f},{0.f,0.f,0.f,0.f}};

    for (int kt = 0; kt <= qt; kt++) {
        const int k0 = kt * 64;
        __syncthreads();

#pragma unroll
        for (int it = 0; it < 4; it++) {
            int idx = tid + it * 256;
            int c = idx >> 4, d4 = (idx & 15) * 4;
            const size_t row = (size_t)(b * SEQ + k0 + c) * KVD + kvh * HD + d4;
            float4 kk = *(const float4*)(K + row);
            Kts[(d4 + 0) * 68 + c] = kk.x;
            Kts[(d4 + 1) * 68 + c] = kk.y;
            Kts[(d4 + 2) * 68 + c] = kk.z;
            Kts[(d4 + 3) * 68 + c] = kk.w;
            float4 vv = *(const float4*)(V + row);
            *(float4*)&Vs[c * 64 + d4] = vv;
        }
        if (tid < 64) kval[tid] = (mask[b * SEQ + k0 + tid] > 0) ? 1.0f : 0.0f;
        __syncthreads();

        float s[4][4] = {{0.f,0.f,0.f,0.f},{0.f,0.f,0.f,0.f},{0.f,0.f,0.f,0.f},{0.f,0.f,0.f,0.f}};
#pragma unroll 8
        for (int d = 0; d < 64; d++) {
            float a0 = Qts[d * 65 + ty * 4 + 0];
            float a1 = Qts[d * 65 + ty * 4 + 1];
            float a2 = Qts[d * 65 + ty * 4 + 2];
            float a3 = Qts[d * 65 + ty * 4 + 3];
            float4 bq = *(const float4*)&Kts[d * 68 + tx * 4];
            s[0][0] = fmaf(a0, bq.x, s[0][0]); s[0][1] = fmaf(a0, bq.y, s[0][1]);
            s[0][2] = fmaf(a0, bq.z, s[0][2]); s[0][3] = fmaf(a0, bq.w, s[0][3]);
            s[1][0] = fmaf(a1, bq.x, s[1][0]); s[1][1] = fmaf(a1, bq.y, s[1][1]);
            s[1][2] = fmaf(a1, bq.z, s[1][2]); s[1][3] = fmaf(a1, bq.w, s[1][3]);
            s[2][0] = fmaf(a2, bq.x, s[2][0]); s[2][1] = fmaf(a2, bq.y, s[2][1]);
            s[2][2] = fmaf(a2, bq.z, s[2][2]); s[2][3] = fmaf(a2, bq.w, s[2][3]);
            s[3][0] = fmaf(a3, bq.x, s[3][0]); s[3][1] = fmaf(a3, bq.y, s[3][1]);
            s[3][2] = fmaf(a3, bq.z, s[3][2]); s[3][3] = fmaf(a3, bq.w, s[3][3]);
        }

#pragma unroll
        for (int i = 0; i < 4; i++) {
            int gq = q0 + ty * 4 + i;
            float mx = -1e30f;
#pragma unroll
            for (int j = 0; j < 4; j++) {
                int gk = k0 + tx * 4 + j;
                bool ok = (gk <= gq) && (kval[tx * 4 + j] > 0.5f);
                s[i][j] = ok ? s[i][j] * scale : -1e30f;
                mx = fmaxf(mx, s[i][j]);
            }
            red[(ty * 4 + i) * 16 + tx] = mx;
        }
        __syncthreads();

        if (tid < 64) {
            float mx = red[tid * 16];
#pragma unroll
            for (int t2 = 1; t2 < 16; t2++) mx = fmaxf(mx, red[tid * 16 + t2]);
            float m_old = m_s[tid];
            float m_new = fmaxf(m_old, mx);
            al_s[tid] = expf(m_old - m_new);
            m_s[tid] = m_new;
        }
        __syncthreads();

        float rs[4];
#pragma unroll
        for (int i = 0; i < 4; i++) {
            float mrow = m_s[ty * 4 + i];
            float acc = 0.0f;
#pragma unroll
            for (int j = 0; j < 4; j++) {
                float p = expf(s[i][j] - mrow);
                Pts[(tx * 4 + j) * 65 + (ty * 4 + i)] = p;
                acc += p;
            }
            rs[i] = acc;
        }
#pragma unroll
        for (int i = 0; i < 4; i++) red[(ty * 4 + i) * 16 + tx] = rs[i];
        __syncthreads();

        if (tid < 64) {
            float sum = 0.0f;
#pragma unroll
            for (int t2 = 0; t2 < 16; t2++) sum += red[tid * 16 + t2];
            l_s[tid] = al_s[tid] * l_s[tid] + sum;
        }
        __syncthreads();

        float al[4];
#pragma unroll
        for (int i = 0; i < 4; i++) al[i] = al_s[ty * 4 + i];
#pragma unroll
        for (int i = 0; i < 4; i++)
#pragma unroll
            for (int j = 0; j < 4; j++) o[i][j] *= al[i];

#pragma unroll 8
        for (int c = 0; c < 64; c++) {
            float a0 = Pts[c * 65 + ty * 4 + 0];
            float a1 = Pts[c * 65 + ty * 4 + 1];
            float a2 = Pts[c * 65 + ty * 4 + 2];
            float a3 = Pts[c * 65 + ty * 4 + 3];
            float4 bv = *(const float4*)&Vs[c * 64 + tx * 4];
            o[0][0] = fmaf(a0, bv.x, o[0][0]); o[0][1] = fmaf(a0, bv.y, o[0][1]);
            o[0][2] = fmaf(a0, bv.z, o[0][2]); o[0][3] = fmaf(a0, bv.w, o[0][3]);
            o[1][0] = fmaf(a1, bv.x, o[1][0]); o[1][1] = fmaf(a1, bv.y, o[1][1]);
            o[1][2] = fmaf(a1, bv.z, o[1][2]); o[1][3] = fmaf(a1, bv.w, o[1][3]);
            o[2][0] = fmaf(a2, bv.x, o[2][0]); o[2][1] = fmaf(a2, bv.y, o[2][1]);
            o[2][2] = fmaf(a2, bv.z, o[2][2]); o[2][3] = fmaf(a2, bv.w, o[2][3]);
            o[3][0] = fmaf(a3, bv.x, o[3][0]); o[3][1] = fmaf(a3, bv.y, o[3][1]);
            o[3][2] = fmaf(a3, bv.z, o[3][2]); o[3][3] = fmaf(a3, bv.w, o[3][3]);
        }
    }

#pragma unroll
    for (int i = 0; i < 4; i++) {
        float inv = 1.0f / l_s[ty * 4 + i];
        float4 w = make_float4(o[i][0] * inv, o[i][1] * inv, o[i][2] * inv, o[i][3] * inv);
        *(float4*)(Oout + (size_t)(b * SEQ + q0 + ty * 4 + i) * DM + h * HD + tx * 4) = w;
    }
}

// ------------------------------------------------------------------
// Launch
// ------------------------------------------------------------------
extern "C" void kernel_launch(void* const* d_in, const int* in_sizes, int n_in,
                              void* d_out, int out_size)
{
    (void)in_sizes; (void)n_in; (void)out_size;
    const float* X    = (const float*)d_in[0];
    const int*   mask = (const int*)  d_in[1];
    const int*   pos  = (const int*)  d_in[2];
    const float* Wq   = (const float*)d_in[3];
    const float* Wk   = (const float*)d_in[4];
    const float* Wv   = (const float*)d_in[5];
    const float* Wo   = (const float*)d_in[6];
    float* out = (float*)d_out;

    float *q, *k, *v, *attn;
    cudaGetSymbolAddress((void**)&q,    g_q);
    cudaGetSymbolAddress((void**)&k,    g_k);
    cudaGetSymbolAddress((void**)&v,    g_v);
    cudaGetSymbolAddress((void**)&attn, g_attn);

    cudaFuncSetAttribute(mma_gemm, cudaFuncAttributeMaxDynamicSharedMemorySize, GEMM_SMEM_BYTES);
    cudaFuncSetAttribute(flash_attn_kernel, cudaFuncAttributeMaxDynamicSharedMemorySize, FA_SMEM_BYTES);

    // QKV projections
    mma_gemm<<<dim3(DM / GBN, TOK / GBM), 512, GEMM_SMEM_BYTES>>>(X, Wq, q, DM, DM);
    mma_gemm<<<dim3(KVD / GBN, TOK / GBM), 512, GEMM_SMEM_BYTES>>>(X, Wk, k, KVD, DM);
    mma_gemm<<<dim3(KVD / GBN, TOK / GBM), 512, GEMM_SMEM_BYTES>>>(X, Wv, v, KVD, DM);

    // RoPE on Q and K
    {
        int total = TOK * ((DM / 2) + (KVD / 2));
        rope_kernel<<<(total + 255) / 256, 256>>>(q, k, pos);
    }

    // Flash attention
    flash_attn_kernel<<<dim3(SEQ / 64, NH, BATCH), 256, FA_SMEM_BYTES>>>(q, k, v, mask, attn);

    // Output projection
    mma_gemm<<<dim3(DM / GBN, TOK / GBM), 512, GEMM_SMEM_BYTES>>>(attn, Wo, out, DM, DM);
}

// round 4
// speedup vs baseline: 2.1792x; 1.5767x over previous
#include <cuda_runtime.h>
#include <cuda_bf16.h>
#include <cstdint>
#include <cstddef>

// Problem constants
#define SEQ   2048
#define BATCH 2
#define TOK   (SEQ * BATCH)   // 4096
#define DM    2048
#define NH    32
#define NKV   8
#define HD    64
#define KVD   (NKV * HD)      // 512

// ------------------------------------------------------------------
// Scratch (device globals; no cudaMalloc allowed)
// ------------------------------------------------------------------
__device__ float g_q[(size_t)TOK * DM];
__device__ float g_k[(size_t)TOK * KVD];
__device__ float g_v[(size_t)TOK * KVD];
__device__ float g_attn[(size_t)TOK * DM];

// Exact fp32 rounding of 10000^(-i/32), i = 0..31
__device__ __constant__ float c_invfreq[32] = {
    1.0f, 0.7498942093324559f, 0.5623413251903491f, 0.4216965034285822f,
    0.31622776601683794f, 0.23713737056616552f, 0.17782794100389228f, 0.1333521432163324f,
    0.1f, 0.07498942093324559f, 0.05623413251903491f, 0.04216965034285822f,
    0.031622776601683794f, 0.023713737056616552f, 0.017782794100389228f, 0.01333521432163324f,
    0.01f, 0.007498942093324559f, 0.005623413251903491f, 0.004216965034285822f,
    0.0031622776601683794f, 0.0023713737056616552f, 0.0017782794100389228f, 0.001333521432163324f,
    0.001f, 0.0007498942093324559f, 0.0005623413251903491f, 0.0004216965034285822f,
    0.00031622776601683794f, 0.00023713737056616552f, 0.00017782794100389228f, 0.0001333521432163324f
};

// ------------------------------------------------------------------
// tf32 helpers (baseline PTX, works on compute_103 virtual arch)
// ------------------------------------------------------------------
__device__ __forceinline__ uint32_t f2tf32(float x) {
    uint32_t r;
    asm("cvt.rna.tf32.f32 %0, %1;" : "=r"(r) : "f"(x));
    return r;
}
__device__ __forceinline__ void mma_tf32(float c[4], const uint32_t a[4], const uint32_t b[2]) {
    asm volatile("mma.sync.aligned.m16n8k8.row.col.f32.tf32.tf32.f32 "
                 "{%0,%1,%2,%3}, {%4,%5,%6,%7}, {%8,%9}, {%0,%1,%2,%3};"
                 : "+f"(c[0]), "+f"(c[1]), "+f"(c[2]), "+f"(c[3])
                 : "r"(a[0]), "r"(a[1]), "r"(a[2]), "r"(a[3]), "r"(b[0]), "r"(b[1]));
}

// ==================================================================
// tf32 mma.sync GEMM (unchanged from round 3)
// ==================================================================
#define GBM 128
#define GBN 128
#define GBK 32
#define AS_U32 (128 * 36)
#define BS_U32 (32 * 136)
#define GEMM_SMEM_BYTES ((AS_U32 + BS_U32) * 2 * 4)  // 71680

__global__ __launch_bounds__(512, 2)
void mma_gemm(const float* __restrict__ A, const float* __restrict__ B,
              float* __restrict__ C, int N, int K)
{
    extern __shared__ uint32_t smu[];
    uint32_t* As = smu;
    uint32_t* Bs = smu + 2 * AS_U32;

    const int tid = threadIdx.x;
    const int wid = tid >> 5, lane = tid & 31;
    const int g = lane >> 2, q = lane & 3;
    const int warp_m = wid >> 2;
    const int warp_n = wid & 3;
    const int m0 = blockIdx.y * GBM, n0 = blockIdx.x * GBN;

    const int arow = tid >> 3;
    const int acol4 = (tid & 7) * 4;
    const int brow = tid >> 5;
    const int bcol4 = (tid & 31) * 4;
    const float* Ag = A + (size_t)(m0 + arow) * K + acol4;
    const float* Bg = B + (size_t)brow * N + n0 + bcol4;

    float acc[2][4][4];
#pragma unroll
    for (int mt = 0; mt < 2; mt++)
#pragma unroll
        for (int nt = 0; nt < 4; nt++)
#pragma unroll
            for (int e = 0; e < 4; e++) acc[mt][nt][e] = 0.0f;

    float4 pa[2], pb[2];
#pragma unroll
    for (int it = 0; it < 2; it++) {
        pa[it] = *(const float4*)(Ag + (size_t)it * 64 * K);
        pb[it] = *(const float4*)(Bg + (size_t)it * 16 * N);
    }
#pragma unroll
    for (int it = 0; it < 2; it++) {
        uint32_t* ap = As + (arow + it * 64) * 36 + acol4;
        ap[0] = f2tf32(pa[it].x); ap[1] = f2tf32(pa[it].y);
        ap[2] = f2tf32(pa[it].z); ap[3] = f2tf32(pa[it].w);
        uint32_t* bp = Bs + (brow + it * 16) * 136 + bcol4;
        bp[0] = f2tf32(pb[it].x); bp[1] = f2tf32(pb[it].y);
        bp[2] = f2tf32(pb[it].z); bp[3] = f2tf32(pb[it].w);
    }
    __syncthreads();

    const int nCh = K / GBK;
    for (int c = 0; c < nCh; c++) {
        const int b = c & 1;
        const uint32_t* as = As + b * AS_U32;
        const uint32_t* bs = Bs + b * BS_U32;

        if (c + 1 < nCh) {
            const int k0 = (c + 1) * GBK;
#pragma unroll
            for (int it = 0; it < 2; it++) {
                pa[it] = *(const float4*)(Ag + k0 + (size_t)it * 64 * K);
                pb[it] = *(const float4*)(Bg + (size_t)(k0 + it * 16) * N);
            }
        }

#pragma unroll
        for (int ks = 0; ks < 4; ks++) {
            uint32_t af[2][4], bf[4][2];
            const int kc = ks * 8 + q;
#pragma unroll
            for (int mt = 0; mt < 2; mt++) {
                const int r0 = warp_m * 32 + mt * 16 + g;
                af[mt][0] = as[r0 * 36 + kc];
                af[mt][1] = as[(r0 + 8) * 36 + kc];
                af[mt][2] = as[r0 * 36 + kc + 4];
                af[mt][3] = as[(r0 + 8) * 36 + kc + 4];
            }
#pragma unroll
            for (int nt = 0; nt < 4; nt++) {
                const int n = warp_n * 32 + nt * 8 + g;
                bf[nt][0] = bs[kc * 136 + n];
                bf[nt][1] = bs[(kc + 4) * 136 + n];
            }
#pragma unroll
            for (int mt = 0; mt < 2; mt++)
#pragma unroll
                for (int nt = 0; nt < 4; nt++)
                    mma_tf32(acc[mt][nt], af[mt], bf[nt]);
        }

        if (c + 1 < nCh) {
            uint32_t* aw = As + (1 - b) * AS_U32;
            uint32_t* bw = Bs + (1 - b) * BS_U32;
#pragma unroll
            for (int it = 0; it < 2; it++) {
                uint32_t* ap = aw + (arow + it * 64) * 36 + acol4;
                ap[0] = f2tf32(pa[it].x); ap[1] = f2tf32(pa[it].y);
                ap[2] = f2tf32(pa[it].z); ap[3] = f2tf32(pa[it].w);
                uint32_t* bp = bw + (brow + it * 16) * 136 + bcol4;
                bp[0] = f2tf32(pb[it].x); bp[1] = f2tf32(pb[it].y);
                bp[2] = f2tf32(pb[it].z); bp[3] = f2tf32(pb[it].w);
            }
        }
        __syncthreads();
    }

#pragma unroll
    for (int mt = 0; mt < 2; mt++) {
#pragma unroll
        for (int nt = 0; nt < 4; nt++) {
            const int row = m0 + warp_m * 32 + mt * 16 + g;
            const int col = n0 + warp_n * 32 + nt * 8 + q * 2;
            *(float2*)(C + (size_t)row * N + col) = make_float2(acc[mt][nt][0], acc[mt][nt][1]);
            *(float2*)(C + (size_t)(row + 8) * N + col) = make_float2(acc[mt][nt][2], acc[mt][nt][3]);
        }
    }
}

// ------------------------------------------------------------------
// RoPE (interleaved pairs), in-place on g_q and g_k.
// ------------------------------------------------------------------
__global__ void rope_kernel(float* __restrict__ Qb, float* __restrict__ Kb,
                            const int* __restrict__ pos_ids)
{
    const int PAIRS_PER_TOK = (DM / 2) + (KVD / 2); // 1280
    int idx = blockIdx.x * blockDim.x + threadIdx.x;
    int total = TOK * PAIRS_PER_TOK;
    if (idx >= total) return;

    int t = idx / PAIRS_PER_TOK;
    int p = idx - t * PAIRS_PER_TOK;

    float* base;
    int i;
    if (p < DM / 2) {
        int head = p >> 5;
        i = p & 31;
        base = Qb + (size_t)t * DM + head * HD + 2 * i;
    } else {
        int pk = p - DM / 2;
        int head = pk >> 5;
        i = pk & 31;
        base = Kb + (size_t)t * KVD + head * HD + 2 * i;
    }

    float pos = (float)pos_ids[t];
    float ang = pos * c_invfreq[i];
    float s, c;
    sincosf(ang, &s, &c);
    float x0 = base[0], x1 = base[1];
    base[0] = fmaf(x0, c, -x1 * s);
    base[1] = fmaf(x0, s,  x1 * c);
}

// ==================================================================
// Tensor-core flash attention (tf32 mma.sync), causal + mask, GQA.
// Block: q-tile 128 x head x batch. 256 threads = 8 warps;
// warp w owns q rows [w*16, w*16+16). K/V tiles of 64.
// Q A-fragments pre-scaled (1/8) and register-resident.
// ==================================================================
#define FA_KS_PAD 68
#define FA_VS_PAD 72
#define FA_PS_PAD 68
#define FA2_SMEM_U32 (64 * FA_KS_PAD + 64 * FA_VS_PAD + 128 * FA_PS_PAD + 64)
#define FA2_SMEM_BYTES (FA2_SMEM_U32 * 4)   // 70912

__global__ __launch_bounds__(256, 2)
void fa_mma_kernel(const float* __restrict__ Q, const float* __restrict__ K,
                   const float* __restrict__ V, const int* __restrict__ mask,
                   float* __restrict__ Oout)
{
    extern __shared__ uint32_t su[];
    uint32_t* Ks = su;                          // [64][68] tf32
    uint32_t* Vs = Ks + 64 * FA_KS_PAD;         // [64][72] tf32
    uint32_t* Ps = Vs + 64 * FA_VS_PAD;         // [128][68] tf32 (per-warp rows)
    float*    kb = (float*)(Ps + 128 * FA_PS_PAD); // [64] additive mask bias

    const int tid = threadIdx.x;
    const int wid = tid >> 5, lane = tid & 31;
    const int g = lane >> 2, q = lane & 3;
    const int qt = blockIdx.x, h = blockIdx.y, b = blockIdx.z;
    const int q0 = qt * 128;
    const int kvh = h >> 2;
    const int row0 = q0 + wid * 16 + g;         // this thread's rows: row0, row0+8

    // Q fragments, pre-scaled by 1/8 (exact power of two; same tf32 rounding)
    uint32_t qa[8][4];
    {
        const float* Qr0 = Q + ((size_t)(b * SEQ) + row0) * DM + h * HD;
        const float* Qr1 = Qr0 + (size_t)8 * DM;
#pragma unroll
        for (int ks = 0; ks < 8; ks++) {
            qa[ks][0] = f2tf32(Qr0[ks * 8 + q] * 0.125f);
            qa[ks][1] = f2tf32(Qr1[ks * 8 + q] * 0.125f);
            qa[ks][2] = f2tf32(Qr0[ks * 8 + q + 4] * 0.125f);
            qa[ks][3] = f2tf32(Qr1[ks * 8 + q + 4] * 0.125f);
        }
    }

    float m0r = -1e30f, m1r = -1e30f;
    float l0r = 0.0f,  l1r = 0.0f;
    float oc[8][4];
#pragma unroll
    for (int nt = 0; nt < 8; nt++)
#pragma unroll
        for (int e = 0; e < 4; e++) oc[nt][e] = 0.0f;

    uint32_t* Pw = Ps + (wid * 16) * FA_PS_PAD;

    const int ktmax = 2 * qt + 1;
    for (int kt = 0; kt <= ktmax; kt++) {
        const int k0 = kt * 64;
        __syncthreads();

        // Load K and V tiles (64 x 64), tf32-converted
#pragma unroll
        for (int it = 0; it < 4; it++) {
            int idx = tid + it * 256;
            int r = idx >> 4, c4 = (idx & 15) * 4;
            const size_t grow = ((size_t)(b * SEQ) + k0 + r) * KVD + kvh * HD + c4;
            float4 kk = *(const float4*)(K + grow);
            uint32_t* kp = Ks + r * FA_KS_PAD + c4;
            kp[0] = f2tf32(kk.x); kp[1] = f2tf32(kk.y);
            kp[2] = f2tf32(kk.z); kp[3] = f2tf32(kk.w);
            float4 vv = *(const float4*)(V + grow);
            uint32_t* vp = Vs + r * FA_VS_PAD + c4;
            vp[0] = f2tf32(vv.x); vp[1] = f2tf32(vv.y);
            vp[2] = f2tf32(vv.z); vp[3] = f2tf32(vv.w);
        }
        if (tid < 64)
            kb[tid] = (mask[b * SEQ + k0 + tid] > 0) ? 0.0f : -1e30f;
        __syncthreads();

        // S = (Q/8) @ K^T
        float sc[8][4];
#pragma unroll
        for (int nt = 0; nt < 8; nt++)
#pragma unroll
            for (int e = 0; e < 4; e++) sc[nt][e] = 0.0f;

#pragma unroll
        for (int ks = 0; ks < 8; ks++) {
            const int kc = ks * 8 + q;
#pragma unroll
            for (int nt = 0; nt < 8; nt++) {
                uint32_t bq[2];
                bq[0] = Ks[(nt * 8 + g) * FA_KS_PAD + kc];
                bq[1] = Ks[(nt * 8 + g) * FA_KS_PAD + kc + 4];
                mma_tf32(sc[nt], qa[ks], bq);
            }
        }

        // causal + mask bias
#pragma unroll
        for (int nt = 0; nt < 8; nt++) {
            const int c0 = k0 + nt * 8 + 2 * q;
            const float kb0 = kb[nt * 8 + 2 * q];
            const float kb1 = kb[nt * 8 + 2 * q + 1];
            sc[nt][0] = (c0     <= row0    ) ? sc[nt][0] + kb0 : -1e30f;
            sc[nt][1] = (c0 + 1 <= row0    ) ? sc[nt][1] + kb1 : -1e30f;
            sc[nt][2] = (c0     <= row0 + 8) ? sc[nt][2] + kb0 : -1e30f;
            sc[nt][3] = (c0 + 1 <= row0 + 8) ? sc[nt][3] + kb1 : -1e30f;
        }

        // row maxes (thread-local then quad shfl)
        float mx0 = -1e30f, mx1 = -1e30f;
#pragma unroll
        for (int nt = 0; nt < 8; nt++) {
            mx0 = fmaxf(mx0, fmaxf(sc[nt][0], sc[nt][1]));
            mx1 = fmaxf(mx1, fmaxf(sc[nt][2], sc[nt][3]));
        }
        mx0 = fmaxf(mx0, __shfl_xor_sync(0xffffffffu, mx0, 1));
        mx0 = fmaxf(mx0, __shfl_xor_sync(0xffffffffu, mx0, 2));
        mx1 = fmaxf(mx1, __shfl_xor_sync(0xffffffffu, mx1, 1));
        mx1 = fmaxf(mx1, __shfl_xor_sync(0xffffffffu, mx1, 2));

        const float mn0 = fmaxf(m0r, mx0);
        const float mn1 = fmaxf(m1r, mx1);
        const float al0 = __expf(m0r - mn0);
        const float al1 = __expf(m1r - mn1);
        m0r = mn0; m1r = mn1;

        // P = exp(S - m): store tf32 to warp-private smem, accumulate sums
        float s0 = 0.0f, s1 = 0.0f;
#pragma unroll
        for (int nt = 0; nt < 8; nt++) {
            float p0 = __expf(sc[nt][0] - mn0);
            float p1 = __expf(sc[nt][1] - mn0);
            float p2 = __expf(sc[nt][2] - mn1);
            float p3 = __expf(sc[nt][3] - mn1);
            s0 += p0 + p1; s1 += p2 + p3;
            const int col = nt * 8 + 2 * q;
            Pw[g * FA_PS_PAD + col]           = f2tf32(p0);
            Pw[g * FA_PS_PAD + col + 1]       = f2tf32(p1);
            Pw[(g + 8) * FA_PS_PAD + col]     = f2tf32(p2);
            Pw[(g + 8) * FA_PS_PAD + col + 1] = f2tf32(p3);
        }
        s0 += __shfl_xor_sync(0xffffffffu, s0, 1);
        s0 += __shfl_xor_sync(0xffffffffu, s0, 2);
        s1 += __shfl_xor_sync(0xffffffffu, s1, 1);
        s1 += __shfl_xor_sync(0xffffffffu, s1, 2);
        l0r = al0 * l0r + s0;
        l1r = al1 * l1r + s1;

        // rescale O
#pragma unroll
        for (int nt = 0; nt < 8; nt++) {
            oc[nt][0] *= al0; oc[nt][1] *= al0;
            oc[nt][2] *= al1; oc[nt][3] *= al1;
        }
        __syncwarp();

        // O += P @ V
#pragma unroll
        for (int ks = 0; ks < 8; ks++) {
            const int kc = ks * 8 + q;
            uint32_t pa[4];
            pa[0] = Pw[g * FA_PS_PAD + kc];
            pa[1] = Pw[(g + 8) * FA_PS_PAD + kc];
            pa[2] = Pw[g * FA_PS_PAD + kc + 4];
            pa[3] = Pw[(g + 8) * FA_PS_PAD + kc + 4];
#pragma unroll
            for (int nt = 0; nt < 8; nt++) {
                uint32_t bv[2];
                bv[0] = Vs[kc * FA_VS_PAD + nt * 8 + g];
                bv[1] = Vs[(kc + 4) * FA_VS_PAD + nt * 8 + g];
                mma_tf32(oc[nt], pa, bv);
            }
        }
    }

    // normalize and write out
    const float inv0 = 1.0f / l0r;
    const float inv1 = 1.0f / l1r;
    float* O0 = Oout + ((size_t)(b * SEQ) + row0) * DM + h * HD;
    float* O1 = O0 + (size_t)8 * DM;
#pragma unroll
    for (int nt = 0; nt < 8; nt++) {
        const int col = nt * 8 + 2 * q;
        *(float2*)(O0 + col) = make_float2(oc[nt][0] * inv0, oc[nt][1] * inv0);
        *(float2*)(O1 + col) = make_float2(oc[nt][2] * inv1, oc[nt][3] * inv1);
    }
}

// ------------------------------------------------------------------
// Launch
// ------------------------------------------------------------------
extern "C" void kernel_launch(void* const* d_in, const int* in_sizes, int n_in,
                              void* d_out, int out_size)
{
    (void)in_sizes; (void)n_in; (void)out_size;
    const float* X    = (const float*)d_in[0];
    const int*   mask = (const int*)  d_in[1];
    const int*   pos  = (const int*)  d_in[2];
    const float* Wq   = (const float*)d_in[3];
    const float* Wk   = (const float*)d_in[4];
    const float* Wv   = (const float*)d_in[5];
    const float* Wo   = (const float*)d_in[6];
    float* out = (float*)d_out;

    float *q, *k, *v, *attn;
    cudaGetSymbolAddress((void**)&q,    g_q);
    cudaGetSymbolAddress((void**)&k,    g_k);
    cudaGetSymbolAddress((void**)&v,    g_v);
    cudaGetSymbolAddress((void**)&attn, g_attn);

    cudaFuncSetAttribute(mma_gemm, cudaFuncAttributeMaxDynamicSharedMemorySize, GEMM_SMEM_BYTES);
    cudaFuncSetAttribute(fa_mma_kernel, cudaFuncAttributeMaxDynamicSharedMemorySize, FA2_SMEM_BYTES);

    // QKV projections
    mma_gemm<<<dim3(DM / GBN, TOK / GBM), 512, GEMM_SMEM_BYTES>>>(X, Wq, q, DM, DM);
    mma_gemm<<<dim3(KVD / GBN, TOK / GBM), 512, GEMM_SMEM_BYTES>>>(X, Wk, k, KVD, DM);
    mma_gemm<<<dim3(KVD / GBN, TOK / GBM), 512, GEMM_SMEM_BYTES>>>(X, Wv, v, KVD, DM);

    // RoPE on Q and K
    {
        int total = TOK * ((DM / 2) + (KVD / 2));
        rope_kernel<<<(total + 255) / 256, 256>>>(q, k, pos);
    }

    // Tensor-core flash attention
    fa_mma_kernel<<<dim3(SEQ / 128, NH, BATCH), 256, FA2_SMEM_BYTES>>>(q, k, v, mask, attn);

    // Output projection
    mma_gemm<<<dim3(DM / GBN, TOK / GBM), 512, GEMM_SMEM_BYTES>>>(attn, Wo, out, DM, DM);
}

// round 5
// speedup vs baseline: 2.5871x; 1.1872x over previous
#include <cuda_runtime.h>
#include <cuda_bf16.h>
#include <cstdint>
#include <cstddef>

// Problem constants
#define SEQ   2048
#define BATCH 2
#define TOK   (SEQ * BATCH)   // 4096
#define DM    2048
#define NH    32
#define NKV   8
#define HD    64
#define KVD   (NKV * HD)      // 512

// ------------------------------------------------------------------
// Scratch (device globals; no cudaMalloc allowed)
// ------------------------------------------------------------------
__device__ float g_q[(size_t)TOK * DM];
__device__ float g_k[(size_t)TOK * KVD];
__device__ float g_v[(size_t)TOK * KVD];
__device__ float g_attn[(size_t)TOK * DM];

// Exact fp32 rounding of 10000^(-i/32), i = 0..31
__device__ __constant__ float c_invfreq[32] = {
    1.0f, 0.7498942093324559f, 0.5623413251903491f, 0.4216965034285822f,
    0.31622776601683794f, 0.23713737056616552f, 0.17782794100389228f, 0.1333521432163324f,
    0.1f, 0.07498942093324559f, 0.05623413251903491f, 0.04216965034285822f,
    0.031622776601683794f, 0.023713737056616552f, 0.017782794100389228f, 0.01333521432163324f,
    0.01f, 0.007498942093324559f, 0.005623413251903491f, 0.004216965034285822f,
    0.0031622776601683794f, 0.0023713737056616552f, 0.0017782794100389228f, 0.001333521432163324f,
    0.001f, 0.0007498942093324559f, 0.0005623413251903491f, 0.0004216965034285822f,
    0.00031622776601683794f, 0.00023713737056616552f, 0.00017782794100389228f, 0.0001333521432163324f
};

// ------------------------------------------------------------------
// tf32 helpers (baseline PTX, works on compute_103 virtual arch)
// ------------------------------------------------------------------
__device__ __forceinline__ uint32_t f2tf32(float x) {
    uint32_t r;
    asm("cvt.rna.tf32.f32 %0, %1;" : "=r"(r) : "f"(x));
    return r;
}
__device__ __forceinline__ void mma_tf32(float c[4], const uint32_t a[4], const uint32_t b[2]) {
    asm volatile("mma.sync.aligned.m16n8k8.row.col.f32.tf32.tf32.f32 "
                 "{%0,%1,%2,%3}, {%4,%5,%6,%7}, {%8,%9}, {%0,%1,%2,%3};"
                 : "+f"(c[0]), "+f"(c[1]), "+f"(c[2]), "+f"(c[3])
                 : "r"(a[0]), "r"(a[1]), "r"(a[2]), "r"(a[3]), "r"(b[0]), "r"(b[1]));
}

// ==================================================================
// tf32 mma.sync GEMM core (same tiling as round 3/4):
// CTA tile 128x128, K-chunk 32, 512 threads (16 warps, warp 32x32).
// Templated epilogue: ROPE_MODE 0 = plain store, 1 = apply RoPE pair
// rotation in-register before store (cols are even -> (col,col+1) pair).
// ==================================================================
#define GBM 128
#define GBN 128
#define GBK 32
#define AS_U32 (128 * 36)
#define BS_U32 (32 * 136)
#define GEMM_SMEM_BYTES ((AS_U32 + BS_U32) * 2 * 4)  // 71680

template <int ROPE_MODE>
__device__ __forceinline__ void gemm_core(
    const float* __restrict__ A, const float* __restrict__ B,
    float* __restrict__ C, int N, int K, int m0, int n0,
    const int* __restrict__ pos, uint32_t* smu)
{
    uint32_t* As = smu;
    uint32_t* Bs = smu + 2 * AS_U32;

    const int tid = threadIdx.x;
    const int wid = tid >> 5, lane = tid & 31;
    const int g = lane >> 2, q = lane & 3;
    const int warp_m = wid >> 2;
    const int warp_n = wid & 3;

    const int arow = tid >> 3;
    const int acol4 = (tid & 7) * 4;
    const int brow = tid >> 5;
    const int bcol4 = (tid & 31) * 4;
    const float* Ag = A + (size_t)(m0 + arow) * K + acol4;
    const float* Bg = B + (size_t)brow * N + n0 + bcol4;

    float acc[2][4][4];
#pragma unroll
    for (int mt = 0; mt < 2; mt++)
#pragma unroll
        for (int nt = 0; nt < 4; nt++)
#pragma unroll
            for (int e = 0; e < 4; e++) acc[mt][nt][e] = 0.0f;

    float4 pa[2], pb[2];
#pragma unroll
    for (int it = 0; it < 2; it++) {
        pa[it] = *(const float4*)(Ag + (size_t)it * 64 * K);
        pb[it] = *(const float4*)(Bg + (size_t)it * 16 * N);
    }
#pragma unroll
    for (int it = 0; it < 2; it++) {
        uint32_t* ap = As + (arow + it * 64) * 36 + acol4;
        ap[0] = f2tf32(pa[it].x); ap[1] = f2tf32(pa[it].y);
        ap[2] = f2tf32(pa[it].z); ap[3] = f2tf32(pa[it].w);
        uint32_t* bp = Bs + (brow + it * 16) * 136 + bcol4;
        bp[0] = f2tf32(pb[it].x); bp[1] = f2tf32(pb[it].y);
        bp[2] = f2tf32(pb[it].z); bp[3] = f2tf32(pb[it].w);
    }
    __syncthreads();

    const int nCh = K / GBK;
    for (int c = 0; c < nCh; c++) {
        const int b = c & 1;
        const uint32_t* as = As + b * AS_U32;
        const uint32_t* bs = Bs + b * BS_U32;

        if (c + 1 < nCh) {
            const int k0 = (c + 1) * GBK;
#pragma unroll
            for (int it = 0; it < 2; it++) {
                pa[it] = *(const float4*)(Ag + k0 + (size_t)it * 64 * K);
                pb[it] = *(const float4*)(Bg + (size_t)(k0 + it * 16) * N);
            }
        }

#pragma unroll
        for (int ks = 0; ks < 4; ks++) {
            uint32_t af[2][4], bf[4][2];
            const int kc = ks * 8 + q;
#pragma unroll
            for (int mt = 0; mt < 2; mt++) {
                const int r0 = warp_m * 32 + mt * 16 + g;
                af[mt][0] = as[r0 * 36 + kc];
                af[mt][1] = as[(r0 + 8) * 36 + kc];
                af[mt][2] = as[r0 * 36 + kc + 4];
                af[mt][3] = as[(r0 + 8) * 36 + kc + 4];
            }
#pragma unroll
            for (int nt = 0; nt < 4; nt++) {
                const int n = warp_n * 32 + nt * 8 + g;
                bf[nt][0] = bs[kc * 136 + n];
                bf[nt][1] = bs[(kc + 4) * 136 + n];
            }
#pragma unroll
            for (int mt = 0; mt < 2; mt++)
#pragma unroll
                for (int nt = 0; nt < 4; nt++)
                    mma_tf32(acc[mt][nt], af[mt], bf[nt]);
        }

        if (c + 1 < nCh) {
            uint32_t* aw = As + (1 - b) * AS_U32;
            uint32_t* bw = Bs + (1 - b) * BS_U32;
#pragma unroll
            for (int it = 0; it < 2; it++) {
                uint32_t* ap = aw + (arow + it * 64) * 36 + acol4;
                ap[0] = f2tf32(pa[it].x); ap[1] = f2tf32(pa[it].y);
                ap[2] = f2tf32(pa[it].z); ap[3] = f2tf32(pa[it].w);
                uint32_t* bp = bw + (brow + it * 16) * 136 + bcol4;
                bp[0] = f2tf32(pb[it].x); bp[1] = f2tf32(pb[it].y);
                bp[2] = f2tf32(pb[it].z); bp[3] = f2tf32(pb[it].w);
            }
        }
        __syncthreads();
    }

    // epilogue: thread owns pairs (col, col+1) at rows (row, row+8)
#pragma unroll
    for (int mt = 0; mt < 2; mt++) {
        const int row = m0 + warp_m * 32 + mt * 16 + g;
        float p0 = 0.0f, p1 = 0.0f;
        if (ROPE_MODE) {
            p0 = (float)pos[row];
            p1 = (float)pos[row + 8];
        }
#pragma unroll
        for (int nt = 0; nt < 4; nt++) {
            const int col = n0 + warp_n * 32 + nt * 8 + q * 2;
            float v00 = acc[mt][nt][0], v01 = acc[mt][nt][1];
            float v10 = acc[mt][nt][2], v11 = acc[mt][nt][3];
            if (ROPE_MODE) {
                const int i = (col & 63) >> 1;   // RoPE pair index within head
                const float f = c_invfreq[i];
                float s0, c0, s1, c1;
                sincosf(p0 * f, &s0, &c0);
                sincosf(p1 * f, &s1, &c1);
                float o00 = fmaf(v00, c0, -v01 * s0);
                float o01 = fmaf(v00, s0,  v01 * c0);
                float o10 = fmaf(v10, c1, -v11 * s1);
                float o11 = fmaf(v10, s1,  v11 * c1);
                v00 = o00; v01 = o01; v10 = o10; v11 = o11;
            }
            *(float2*)(C + (size_t)row * N + col)       = make_float2(v00, v01);
            *(float2*)(C + (size_t)(row + 8) * N + col) = make_float2(v10, v11);
        }
    }
}

// Plain GEMM (O projection)
__global__ __launch_bounds__(512, 2)
void mma_gemm(const float* __restrict__ A, const float* __restrict__ B,
              float* __restrict__ C, int N, int K)
{
    extern __shared__ uint32_t smu[];
    gemm_core<0>(A, B, C, N, K, blockIdx.y * GBM, blockIdx.x * GBN, nullptr, smu);
}

// Fused QKV projection + RoPE.
// grid.x in [0,24): 0-15 -> Q (Wq, rope), 16-19 -> K (Wk, rope), 20-23 -> V (Wv).
__global__ __launch_bounds__(512, 2)
void mma_gemm_qkv(const float* __restrict__ X,
                  const float* __restrict__ Wq, const float* __restrict__ Wk,
                  const float* __restrict__ Wv,
                  float* __restrict__ Cq, float* __restrict__ Ck, float* __restrict__ Cv,
                  const int* __restrict__ pos)
{
    extern __shared__ uint32_t smu[];
    const int bx = blockIdx.x;
    const int m0 = blockIdx.y * GBM;
    if (bx < 16) {
        gemm_core<1>(X, Wq, Cq, DM, DM, m0, bx * GBN, pos, smu);
    } else if (bx < 20) {
        gemm_core<1>(X, Wk, Ck, KVD, DM, m0, (bx - 16) * GBN, pos, smu);
    } else {
        gemm_core<0>(X, Wv, Cv, KVD, DM, m0, (bx - 20) * GBN, nullptr, smu);
    }
}

// ==================================================================
// Tensor-core flash attention (tf32 mma.sync), causal + mask, GQA.
// (unchanged from round 4)
// ==================================================================
#define FA_KS_PAD 68
#define FA_VS_PAD 72
#define FA_PS_PAD 68
#define FA2_SMEM_U32 (64 * FA_KS_PAD + 64 * FA_VS_PAD + 128 * FA_PS_PAD + 64)
#define FA2_SMEM_BYTES (FA2_SMEM_U32 * 4)   // 70912

__global__ __launch_bounds__(256, 2)
void fa_mma_kernel(const float* __restrict__ Q, const float* __restrict__ K,
                   const float* __restrict__ V, const int* __restrict__ mask,
                   float* __restrict__ Oout)
{
    extern __shared__ uint32_t su[];
    uint32_t* Ks = su;
    uint32_t* Vs = Ks + 64 * FA_KS_PAD;
    uint32_t* Ps = Vs + 64 * FA_VS_PAD;
    float*    kb = (float*)(Ps + 128 * FA_PS_PAD);

    const int tid = threadIdx.x;
    const int wid = tid >> 5, lane = tid & 31;
    const int g = lane >> 2, q = lane & 3;
    const int qt = blockIdx.x, h = blockIdx.y, b = blockIdx.z;
    const int q0 = qt * 128;
    const int kvh = h >> 2;
    const int row0 = q0 + wid * 16 + g;

    uint32_t qa[8][4];
    {
        const float* Qr0 = Q + ((size_t)(b * SEQ) + row0) * DM + h * HD;
        const float* Qr1 = Qr0 + (size_t)8 * DM;
#pragma unroll
        for (int ks = 0; ks < 8; ks++) {
            qa[ks][0] = f2tf32(Qr0[ks * 8 + q] * 0.125f);
            qa[ks][1] = f2tf32(Qr1[ks * 8 + q] * 0.125f);
            qa[ks][2] = f2tf32(Qr0[ks * 8 + q + 4] * 0.125f);
            qa[ks][3] = f2tf32(Qr1[ks * 8 + q + 4] * 0.125f);
        }
    }

    float m0r = -1e30f, m1r = -1e30f;
    float l0r = 0.0f,  l1r = 0.0f;
    float oc[8][4];
#pragma unroll
    for (int nt = 0; nt < 8; nt++)
#pragma unroll
        for (int e = 0; e < 4; e++) oc[nt][e] = 0.0f;

    uint32_t* Pw = Ps + (wid * 16) * FA_PS_PAD;

    const int ktmax = 2 * qt + 1;
    for (int kt = 0; kt <= ktmax; kt++) {
        const int k0 = kt * 64;
        __syncthreads();

#pragma unroll
        for (int it = 0; it < 4; it++) {
            int idx = tid + it * 256;
            int r = idx >> 4, c4 = (idx & 15) * 4;
            const size_t grow = ((size_t)(b * SEQ) + k0 + r) * KVD + kvh * HD + c4;
            float4 kk = *(const float4*)(K + grow);
            uint32_t* kp = Ks + r * FA_KS_PAD + c4;
            kp[0] = f2tf32(kk.x); kp[1] = f2tf32(kk.y);
            kp[2] = f2tf32(kk.z); kp[3] = f2tf32(kk.w);
            float4 vv = *(const float4*)(V + grow);
            uint32_t* vp = Vs + r * FA_VS_PAD + c4;
            vp[0] = f2tf32(vv.x); vp[1] = f2tf32(vv.y);
            vp[2] = f2tf32(vv.z); vp[3] = f2tf32(vv.w);
        }
        if (tid < 64)
            kb[tid] = (mask[b * SEQ + k0 + tid] > 0) ? 0.0f : -1e30f;
        __syncthreads();

        float sc[8][4];
#pragma unroll
        for (int nt = 0; nt < 8; nt++)
#pragma unroll
            for (int e = 0; e < 4; e++) sc[nt][e] = 0.0f;

#pragma unroll
        for (int ks = 0; ks < 8; ks++) {
            const int kc = ks * 8 + q;
#pragma unroll
            for (int nt = 0; nt < 8; nt++) {
                uint32_t bq[2];
                bq[0] = Ks[(nt * 8 + g) * FA_KS_PAD + kc];
                bq[1] = Ks[(nt * 8 + g) * FA_KS_PAD + kc + 4];
                mma_tf32(sc[nt], qa[ks], bq);
            }
        }

#pragma unroll
        for (int nt = 0; nt < 8; nt++) {
            const int c0 = k0 + nt * 8 + 2 * q;
            const float kb0 = kb[nt * 8 + 2 * q];
            const float kb1 = kb[nt * 8 + 2 * q + 1];
            sc[nt][0] = (c0     <= row0    ) ? sc[nt][0] + kb0 : -1e30f;
            sc[nt][1] = (c0 + 1 <= row0    ) ? sc[nt][1] + kb1 : -1e30f;
            sc[nt][2] = (c0     <= row0 + 8) ? sc[nt][2] + kb0 : -1e30f;
            sc[nt][3] = (c0 + 1 <= row0 + 8) ? sc[nt][3] + kb1 : -1e30f;
        }

        float mx0 = -1e30f, mx1 = -1e30f;
#pragma unroll
        for (int nt = 0; nt < 8; nt++) {
            mx0 = fmaxf(mx0, fmaxf(sc[nt][0], sc[nt][1]));
            mx1 = fmaxf(mx1, fmaxf(sc[nt][2], sc[nt][3]));
        }
        mx0 = fmaxf(mx0, __shfl_xor_sync(0xffffffffu, mx0, 1));
        mx0 = fmaxf(mx0, __shfl_xor_sync(0xffffffffu, mx0, 2));
        mx1 = fmaxf(mx1, __shfl_xor_sync(0xffffffffu, mx1, 1));
        mx1 = fmaxf(mx1, __shfl_xor_sync(0xffffffffu, mx1, 2));

        const float mn0 = fmaxf(m0r, mx0);
        const float mn1 = fmaxf(m1r, mx1);
        const float al0 = __expf(m0r - mn0);
        const float al1 = __expf(m1r - mn1);
        m0r = mn0; m1r = mn1;

        float s0 = 0.0f, s1 = 0.0f;
#pragma unroll
        for (int nt = 0; nt < 8; nt++) {
            float p0 = __expf(sc[nt][0] - mn0);
            float p1 = __expf(sc[nt][1] - mn0);
            float p2 = __expf(sc[nt][2] - mn1);
            float p3 = __expf(sc[nt][3] - mn1);
            s0 += p0 + p1; s1 += p2 + p3;
            const int col = nt * 8 + 2 * q;
            Pw[g * FA_PS_PAD + col]           = f2tf32(p0);
            Pw[g * FA_PS_PAD + col + 1]       = f2tf32(p1);
            Pw[(g + 8) * FA_PS_PAD + col]     = f2tf32(p2);
            Pw[(g + 8) * FA_PS_PAD + col + 1] = f2tf32(p3);
        }
        s0 += __shfl_xor_sync(0xffffffffu, s0, 1);
        s0 += __shfl_xor_sync(0xffffffffu, s0, 2);
        s1 += __shfl_xor_sync(0xffffffffu, s1, 1);
        s1 += __shfl_xor_sync(0xffffffffu, s1, 2);
        l0r = al0 * l0r + s0;
        l1r = al1 * l1r + s1;

#pragma unroll
        for (int nt = 0; nt < 8; nt++) {
            oc[nt][0] *= al0; oc[nt][1] *= al0;
            oc[nt][2] *= al1; oc[nt][3] *= al1;
        }
        __syncwarp();

#pragma unroll
        for (int ks = 0; ks < 8; ks++) {
            const int kc = ks * 8 + q;
            uint32_t pa[4];
            pa[0] = Pw[g * FA_PS_PAD + kc];
            pa[1] = Pw[(g + 8) * FA_PS_PAD + kc];
            pa[2] = Pw[g * FA_PS_PAD + kc + 4];
            pa[3] = Pw[(g + 8) * FA_PS_PAD + kc + 4];
#pragma unroll
            for (int nt = 0; nt < 8; nt++) {
                uint32_t bv[2];
                bv[0] = Vs[kc * FA_VS_PAD + nt * 8 + g];
                bv[1] = Vs[(kc + 4) * FA_VS_PAD + nt * 8 + g];
                mma_tf32(oc[nt], pa, bv);
            }
        }
    }

    const float inv0 = 1.0f / l0r;
    const float inv1 = 1.0f / l1r;
    float* O0 = Oout + ((size_t)(b * SEQ) + row0) * DM + h * HD;
    float* O1 = O0 + (size_t)8 * DM;
#pragma unroll
    for (int nt = 0; nt < 8; nt++) {
        const int col = nt * 8 + 2 * q;
        *(float2*)(O0 + col) = make_float2(oc[nt][0] * inv0, oc[nt][1] * inv0);
        *(float2*)(O1 + col) = make_float2(oc[nt][2] * inv1, oc[nt][3] * inv1);
    }
}

// ------------------------------------------------------------------
// Launch
// ------------------------------------------------------------------
extern "C" void kernel_launch(void* const* d_in, const int* in_sizes, int n_in,
                              void* d_out, int out_size)
{
    (void)in_sizes; (void)n_in; (void)out_size;
    const float* X    = (const float*)d_in[0];
    const int*   mask = (const int*)  d_in[1];
    const int*   pos  = (const int*)  d_in[2];
    const float* Wq   = (const float*)d_in[3];
    const float* Wk   = (const float*)d_in[4];
    const float* Wv   = (const float*)d_in[5];
    const float* Wo   = (const float*)d_in[6];
    float* out = (float*)d_out;

    float *q, *k, *v, *attn;
    cudaGetSymbolAddress((void**)&q,    g_q);
    cudaGetSymbolAddress((void**)&k,    g_k);
    cudaGetSymbolAddress((void**)&v,    g_v);
    cudaGetSymbolAddress((void**)&attn, g_attn);

    cudaFuncSetAttribute(mma_gemm, cudaFuncAttributeMaxDynamicSharedMemorySize, GEMM_SMEM_BYTES);
    cudaFuncSetAttribute(mma_gemm_qkv, cudaFuncAttributeMaxDynamicSharedMemorySize, GEMM_SMEM_BYTES);
    cudaFuncSetAttribute(fa_mma_kernel, cudaFuncAttributeMaxDynamicSharedMemorySize, FA2_SMEM_BYTES);

    // Fused QKV projections + RoPE (24 column tiles: 16 Q, 4 K, 4 V)
    mma_gemm_qkv<<<dim3(24, TOK / GBM), 512, GEMM_SMEM_BYTES>>>(X, Wq, Wk, Wv, q, k, v, pos);

    // Tensor-core flash attention
    fa_mma_kernel<<<dim3(SEQ / 128, NH, BATCH), 256, FA2_SMEM_BYTES>>>(q, k, v, mask, attn);

    // Output projection
    mma_gemm<<<dim3(DM / GBN, TOK / GBM), 512, GEMM_SMEM_BYTES>>>(attn, Wo, out, DM, DM);
}

// round 6
// speedup vs baseline: 3.5117x; 1.3574x over previous
#include <cuda_runtime.h>
#include <cuda_bf16.h>
#include <cstdint>
#include <cstddef>

// Problem constants
#define SEQ   2048
#define BATCH 2
#define TOK   (SEQ * BATCH)   // 4096
#define DM    2048
#define NH    32
#define NKV   8
#define HD    64
#define KVD   (NKV * HD)      // 512

// ------------------------------------------------------------------
// Scratch (device globals; no cudaMalloc allowed)
// ------------------------------------------------------------------
__device__ float g_q[(size_t)TOK * DM];
__device__ float g_k[(size_t)TOK * KVD];
__device__ float g_v[(size_t)TOK * KVD];
__device__ float g_attn[(size_t)TOK * DM];

// Exact fp32 rounding of 10000^(-i/32), i = 0..31
__device__ __constant__ float c_invfreq[32] = {
    1.0f, 0.7498942093324559f, 0.5623413251903491f, 0.4216965034285822f,
    0.31622776601683794f, 0.23713737056616552f, 0.17782794100389228f, 0.1333521432163324f,
    0.1f, 0.07498942093324559f, 0.05623413251903491f, 0.04216965034285822f,
    0.031622776601683794f, 0.023713737056616552f, 0.017782794100389228f, 0.01333521432163324f,
    0.01f, 0.007498942093324559f, 0.005623413251903491f, 0.004216965034285822f,
    0.0031622776601683794f, 0.0023713737056616552f, 0.0017782794100389228f, 0.001333521432163324f,
    0.001f, 0.0007498942093324559f, 0.0005623413251903491f, 0.0004216965034285822f,
    0.00031622776601683794f, 0.00023713737056616552f, 0.00017782794100389228f, 0.0001333521432163324f
};

// ------------------------------------------------------------------
// tf32 helpers (baseline PTX, works on compute_103 virtual arch)
// ------------------------------------------------------------------
__device__ __forceinline__ uint32_t f2tf32(float x) {
    uint32_t r;
    asm("cvt.rna.tf32.f32 %0, %1;" : "=r"(r) : "f"(x));
    return r;
}
__device__ __forceinline__ void mma_tf32(float c[4], const uint32_t a[4], const uint32_t b[2]) {
    asm volatile("mma.sync.aligned.m16n8k8.row.col.f32.tf32.tf32.f32 "
                 "{%0,%1,%2,%3}, {%4,%5,%6,%7}, {%8,%9}, {%0,%1,%2,%3};"
                 : "+f"(c[0]), "+f"(c[1]), "+f"(c[2]), "+f"(c[3])
                 : "r"(a[0]), "r"(a[1]), "r"(a[2]), "r"(a[3]), "r"(b[0]), "r"(b[1]));
}

// ==================================================================
// tf32 mma.sync GEMM core, round 6 tiling:
// CTA tile 256x128, K-chunk 32, 512 threads = 16 warps (4x4),
// warp tile 64x32 (mt=4, nt=4) -> 0.1875 smem bytes/MAC (was 0.25).
// Double-buffered smem + register prefetch. 1 CTA/SM.
// Templated epilogue: ROPE_MODE 1 applies interleaved RoPE rotation.
// ==================================================================
#define GBM 256
#define GBN 128
#define GBK 32
#define AS_U32 (256 * 36)   // 9216
#define BS_U32 (32 * 136)   // 4352
#define GEMM_SMEM_BYTES ((AS_U32 + BS_U32) * 2 * 4)  // 108544

template <int ROPE_MODE>
__device__ __forceinline__ void gemm_core(
    const float* __restrict__ A, const float* __restrict__ B,
    float* __restrict__ C, int N, int K, int m0, int n0,
    const int* __restrict__ pos, uint32_t* smu)
{
    uint32_t* As = smu;
    uint32_t* Bs = smu + 2 * AS_U32;

    const int tid = threadIdx.x;
    const int wid = tid >> 5, lane = tid & 31;
    const int g = lane >> 2, q = lane & 3;
    const int warp_m = wid >> 2;           // 0..3 (64 rows each)
    const int warp_n = wid & 3;            // 0..3 (32 cols each)

    // global load addressing:
    // A tile 256x32: arow = tid>>3 (0..63), 4 row-groups of 64; acol4 = (tid&7)*4
    // B tile 32x128: brow = tid>>5 (0..15), 2 row-groups of 16; bcol4 = (tid&31)*4
    const int arow = tid >> 3;
    const int acol4 = (tid & 7) * 4;
    const int brow = tid >> 5;
    const int bcol4 = (tid & 31) * 4;
    const float* Ag = A + (size_t)(m0 + arow) * K + acol4;
    const float* Bg = B + (size_t)brow * N + n0 + bcol4;

    float acc[4][4][4];
#pragma unroll
    for (int mt = 0; mt < 4; mt++)
#pragma unroll
        for (int nt = 0; nt < 4; nt++)
#pragma unroll
            for (int e = 0; e < 4; e++) acc[mt][nt][e] = 0.0f;

    float4 pa[4], pb[2];
#pragma unroll
    for (int it = 0; it < 4; it++)
        pa[it] = *(const float4*)(Ag + (size_t)it * 64 * K);
#pragma unroll
    for (int it = 0; it < 2; it++)
        pb[it] = *(const float4*)(Bg + (size_t)it * 16 * N);

#pragma unroll
    for (int it = 0; it < 4; it++) {
        uint32_t* ap = As + (arow + it * 64) * 36 + acol4;
        ap[0] = f2tf32(pa[it].x); ap[1] = f2tf32(pa[it].y);
        ap[2] = f2tf32(pa[it].z); ap[3] = f2tf32(pa[it].w);
    }
#pragma unroll
    for (int it = 0; it < 2; it++) {
        uint32_t* bp = Bs + (brow + it * 16) * 136 + bcol4;
        bp[0] = f2tf32(pb[it].x); bp[1] = f2tf32(pb[it].y);
        bp[2] = f2tf32(pb[it].z); bp[3] = f2tf32(pb[it].w);
    }
    __syncthreads();

    const int nCh = K / GBK;
    for (int c = 0; c < nCh; c++) {
        const int b = c & 1;
        const uint32_t* as = As + b * AS_U32;
        const uint32_t* bs = Bs + b * BS_U32;

        if (c + 1 < nCh) {
            const int k0 = (c + 1) * GBK;
#pragma unroll
            for (int it = 0; it < 4; it++)
                pa[it] = *(const float4*)(Ag + k0 + (size_t)it * 64 * K);
#pragma unroll
            for (int it = 0; it < 2; it++)
                pb[it] = *(const float4*)(Bg + (size_t)(k0 + it * 16) * N);
        }

#pragma unroll
        for (int ks = 0; ks < 4; ks++) {
            uint32_t af[4][4], bf[4][2];
            const int kc = ks * 8 + q;
#pragma unroll
            for (int mt = 0; mt < 4; mt++) {
                const int r0 = warp_m * 64 + mt * 16 + g;
                af[mt][0] = as[r0 * 36 + kc];
                af[mt][1] = as[(r0 + 8) * 36 + kc];
                af[mt][2] = as[r0 * 36 + kc + 4];
                af[mt][3] = as[(r0 + 8) * 36 + kc + 4];
            }
#pragma unroll
            for (int nt = 0; nt < 4; nt++) {
                const int n = warp_n * 32 + nt * 8 + g;
                bf[nt][0] = bs[kc * 136 + n];
                bf[nt][1] = bs[(kc + 4) * 136 + n];
            }
#pragma unroll
            for (int mt = 0; mt < 4; mt++)
#pragma unroll
                for (int nt = 0; nt < 4; nt++)
                    mma_tf32(acc[mt][nt], af[mt], bf[nt]);
        }

        if (c + 1 < nCh) {
            uint32_t* aw = As + (1 - b) * AS_U32;
            uint32_t* bw = Bs + (1 - b) * BS_U32;
#pragma unroll
            for (int it = 0; it < 4; it++) {
                uint32_t* ap = aw + (arow + it * 64) * 36 + acol4;
                ap[0] = f2tf32(pa[it].x); ap[1] = f2tf32(pa[it].y);
                ap[2] = f2tf32(pa[it].z); ap[3] = f2tf32(pa[it].w);
            }
#pragma unroll
            for (int it = 0; it < 2; it++) {
                uint32_t* bp = bw + (brow + it * 16) * 136 + bcol4;
                bp[0] = f2tf32(pb[it].x); bp[1] = f2tf32(pb[it].y);
                bp[2] = f2tf32(pb[it].z); bp[3] = f2tf32(pb[it].w);
            }
        }
        __syncthreads();
    }

    // epilogue: thread owns pairs (col, col+1) at rows (row, row+8)
#pragma unroll
    for (int mt = 0; mt < 4; mt++) {
        const int row = m0 + warp_m * 64 + mt * 16 + g;
        float p0 = 0.0f, p1 = 0.0f;
        if (ROPE_MODE) {
            p0 = (float)pos[row];
            p1 = (float)pos[row + 8];
        }
#pragma unroll
        for (int nt = 0; nt < 4; nt++) {
            const int col = n0 + warp_n * 32 + nt * 8 + q * 2;
            float v00 = acc[mt][nt][0], v01 = acc[mt][nt][1];
            float v10 = acc[mt][nt][2], v11 = acc[mt][nt][3];
            if (ROPE_MODE) {
                const int i = (col & 63) >> 1;   // RoPE pair index within head
                const float f = c_invfreq[i];
                float s0, c0, s1, c1;
                sincosf(p0 * f, &s0, &c0);
                sincosf(p1 * f, &s1, &c1);
                float o00 = fmaf(v00, c0, -v01 * s0);
                float o01 = fmaf(v00, s0,  v01 * c0);
                float o10 = fmaf(v10, c1, -v11 * s1);
                float o11 = fmaf(v10, s1,  v11 * c1);
                v00 = o00; v01 = o01; v10 = o10; v11 = o11;
            }
            *(float2*)(C + (size_t)row * N + col)       = make_float2(v00, v01);
            *(float2*)(C + (size_t)(row + 8) * N + col) = make_float2(v10, v11);
        }
    }
}

// Plain GEMM (O projection)
__global__ __launch_bounds__(512, 1)
void mma_gemm(const float* __restrict__ A, const float* __restrict__ B,
              float* __restrict__ C, int N, int K)
{
    extern __shared__ uint32_t smu[];
    gemm_core<0>(A, B, C, N, K, blockIdx.y * GBM, blockIdx.x * GBN, nullptr, smu);
}

// Fused QKV projection + RoPE.
// grid.x in [0,24): 0-15 -> Q (Wq, rope), 16-19 -> K (Wk, rope), 20-23 -> V (Wv).
__global__ __launch_bounds__(512, 1)
void mma_gemm_qkv(const float* __restrict__ X,
                  const float* __restrict__ Wq, const float* __restrict__ Wk,
                  const float* __restrict__ Wv,
                  float* __restrict__ Cq, float* __restrict__ Ck, float* __restrict__ Cv,
                  const int* __restrict__ pos)
{
    extern __shared__ uint32_t smu[];
    const int bx = blockIdx.x;
    const int m0 = blockIdx.y * GBM;
    if (bx < 16) {
        gemm_core<1>(X, Wq, Cq, DM, DM, m0, bx * GBN, pos, smu);
    } else if (bx < 20) {
        gemm_core<1>(X, Wk, Ck, KVD, DM, m0, (bx - 16) * GBN, pos, smu);
    } else {
        gemm_core<0>(X, Wv, Cv, KVD, DM, m0, (bx - 20) * GBN, nullptr, smu);
    }
}

// ==================================================================
// Tensor-core flash attention (tf32 mma.sync), causal + mask, GQA.
// (unchanged from round 4/5)
// ==================================================================
#define FA_KS_PAD 68
#define FA_VS_PAD 72
#define FA_PS_PAD 68
#define FA2_SMEM_U32 (64 * FA_KS_PAD + 64 * FA_VS_PAD + 128 * FA_PS_PAD + 64)
#define FA2_SMEM_BYTES (FA2_SMEM_U32 * 4)   // 70912

__global__ __launch_bounds__(256, 2)
void fa_mma_kernel(const float* __restrict__ Q, const float* __restrict__ K,
                   const float* __restrict__ V, const int* __restrict__ mask,
                   float* __restrict__ Oout)
{
    extern __shared__ uint32_t su[];
    uint32_t* Ks = su;
    uint32_t* Vs = Ks + 64 * FA_KS_PAD;
    uint32_t* Ps = Vs + 64 * FA_VS_PAD;
    float*    kb = (float*)(Ps + 128 * FA_PS_PAD);

    const int tid = threadIdx.x;
    const int wid = tid >> 5, lane = tid & 31;
    const int g = lane >> 2, q = lane & 3;
    const int qt = blockIdx.x, h = blockIdx.y, b = blockIdx.z;
    const int q0 = qt * 128;
    const int kvh = h >> 2;
    const int row0 = q0 + wid * 16 + g;

    uint32_t qa[8][4];
    {
        const float* Qr0 = Q + ((size_t)(b * SEQ) + row0) * DM + h * HD;
        const float* Qr1 = Qr0 + (size_t)8 * DM;
#pragma unroll
        for (int ks = 0; ks < 8; ks++) {
            qa[ks][0] = f2tf32(Qr0[ks * 8 + q] * 0.125f);
            qa[ks][1] = f2tf32(Qr1[ks * 8 + q] * 0.125f);
            qa[ks][2] = f2tf32(Qr0[ks * 8 + q + 4] * 0.125f);
            qa[ks][3] = f2tf32(Qr1[ks * 8 + q + 4] * 0.125f);
        }
    }

    float m0r = -1e30f, m1r = -1e30f;
    float l0r = 0.0f,  l1r = 0.0f;
    float oc[8][4];
#pragma unroll
    for (int nt = 0; nt < 8; nt++)
#pragma unroll
        for (int e = 0; e < 4; e++) oc[nt][e] = 0.0f;

    uint32_t* Pw = Ps + (wid * 16) * FA_PS_PAD;

    const int ktmax = 2 * qt + 1;
    for (int kt = 0; kt <= ktmax; kt++) {
        const int k0 = kt * 64;
        __syncthreads();

#pragma unroll
        for (int it = 0; it < 4; it++) {
            int idx = tid + it * 256;
            int r = idx >> 4, c4 = (idx & 15) * 4;
            const size_t grow = ((size_t)(b * SEQ) + k0 + r) * KVD + kvh * HD + c4;
            float4 kk = *(const float4*)(K + grow);
            uint32_t* kp = Ks + r * FA_KS_PAD + c4;
            kp[0] = f2tf32(kk.x); kp[1] = f2tf32(kk.y);
            kp[2] = f2tf32(kk.z); kp[3] = f2tf32(kk.w);
            float4 vv = *(const float4*)(V + grow);
            uint32_t* vp = Vs + r * FA_VS_PAD + c4;
            vp[0] = f2tf32(vv.x); vp[1] = f2tf32(vv.y);
            vp[2] = f2tf32(vv.z); vp[3] = f2tf32(vv.w);
        }
        if (tid < 64)
            kb[tid] = (mask[b * SEQ + k0 + tid] > 0) ? 0.0f : -1e30f;
        __syncthreads();

        float sc[8][4];
#pragma unroll
        for (int nt = 0; nt < 8; nt++)
#pragma unroll
            for (int e = 0; e < 4; e++) sc[nt][e] = 0.0f;

#pragma unroll
        for (int ks = 0; ks < 8; ks++) {
            const int kc = ks * 8 + q;
#pragma unroll
            for (int nt = 0; nt < 8; nt++) {
                uint32_t bq[2];
                bq[0] = Ks[(nt * 8 + g) * FA_KS_PAD + kc];
                bq[1] = Ks[(nt * 8 + g) * FA_KS_PAD + kc + 4];
                mma_tf32(sc[nt], qa[ks], bq);
            }
        }

#pragma unroll
        for (int nt = 0; nt < 8; nt++) {
            const int c0 = k0 + nt * 8 + 2 * q;
            const float kb0 = kb[nt * 8 + 2 * q];
            const float kb1 = kb[nt * 8 + 2 * q + 1];
            sc[nt][0] = (c0     <= row0    ) ? sc[nt][0] + kb0 : -1e30f;
            sc[nt][1] = (c0 + 1 <= row0    ) ? sc[nt][1] + kb1 : -1e30f;
            sc[nt][2] = (c0     <= row0 + 8) ? sc[nt][2] + kb0 : -1e30f;
            sc[nt][3] = (c0 + 1 <= row0 + 8) ? sc[nt][3] + kb1 : -1e30f;
        }

        float mx0 = -1e30f, mx1 = -1e30f;
#pragma unroll
        for (int nt = 0; nt < 8; nt++) {
            mx0 = fmaxf(mx0, fmaxf(sc[nt][0], sc[nt][1]));
            mx1 = fmaxf(mx1, fmaxf(sc[nt][2], sc[nt][3]));
        }
        mx0 = fmaxf(mx0, __shfl_xor_sync(0xffffffffu, mx0, 1));
        mx0 = fmaxf(mx0, __shfl_xor_sync(0xffffffffu, mx0, 2));
        mx1 = fmaxf(mx1, __shfl_xor_sync(0xffffffffu, mx1, 1));
        mx1 = fmaxf(mx1, __shfl_xor_sync(0xffffffffu, mx1, 2));

        const float mn0 = fmaxf(m0r, mx0);
        const float mn1 = fmaxf(m1r, mx1);
        const float al0 = __expf(m0r - mn0);
        const float al1 = __expf(m1r - mn1);
        m0r = mn0; m1r = mn1;

        float s0 = 0.0f, s1 = 0.0f;
#pragma unroll
        for (int nt = 0; nt < 8; nt++) {
            float p0 = __expf(sc[nt][0] - mn0);
            float p1 = __expf(sc[nt][1] - mn0);
            float p2 = __expf(sc[nt][2] - mn1);
            float p3 = __expf(sc[nt][3] - mn1);
            s0 += p0 + p1; s1 += p2 + p3;
            const int col = nt * 8 + 2 * q;
            Pw[g * FA_PS_PAD + col]           = f2tf32(p0);
            Pw[g * FA_PS_PAD + col + 1]       = f2tf32(p1);
            Pw[(g + 8) * FA_PS_PAD + col]     = f2tf32(p2);
            Pw[(g + 8) * FA_PS_PAD + col + 1] = f2tf32(p3);
        }
        s0 += __shfl_xor_sync(0xffffffffu, s0, 1);
        s0 += __shfl_xor_sync(0xffffffffu, s0, 2);
        s1 += __shfl_xor_sync(0xffffffffu, s1, 1);
        s1 += __shfl_xor_sync(0xffffffffu, s1, 2);
        l0r = al0 * l0r + s0;
        l1r = al1 * l1r + s1;

#pragma unroll
        for (int nt = 0; nt < 8; nt++) {
            oc[nt][0] *= al0; oc[nt][1] *= al0;
            oc[nt][2] *= al1; oc[nt][3] *= al1;
        }
        __syncwarp();

#pragma unroll
        for (int ks = 0; ks < 8; ks++) {
            const int kc = ks * 8 + q;
            uint32_t pa[4];
            pa[0] = Pw[g * FA_PS_PAD + kc];
            pa[1] = Pw[(g + 8) * FA_PS_PAD + kc];
            pa[2] = Pw[g * FA_PS_PAD + kc + 4];
            pa[3] = Pw[(g + 8) * FA_PS_PAD + kc + 4];
#pragma unroll
            for (int nt = 0; nt < 8; nt++) {
                uint32_t bv[2];
                bv[0] = Vs[kc * FA_VS_PAD + nt * 8 + g];
                bv[1] = Vs[(kc + 4) * FA_VS_PAD + nt * 8 + g];
                mma_tf32(oc[nt], pa, bv);
            }
        }
    }

    const float inv0 = 1.0f / l0r;
    const float inv1 = 1.0f / l1r;
    float* O0 = Oout + ((size_t)(b * SEQ) + row0) * DM + h * HD;
    float* O1 = O0 + (size_t)8 * DM;
#pragma unroll
    for (int nt = 0; nt < 8; nt++) {
        const int col = nt * 8 + 2 * q;
        *(float2*)(O0 + col) = make_float2(oc[nt][0] * inv0, oc[nt][1] * inv0);
        *(float2*)(O1 + col) = make_float2(oc[nt][2] * inv1, oc[nt][3] * inv1);
    }
}

// ------------------------------------------------------------------
// Launch
// ------------------------------------------------------------------
extern "C" void kernel_launch(void* const* d_in, const int* in_sizes, int n_in,
                              void* d_out, int out_size)
{
    (void)in_sizes; (void)n_in; (void)out_size;
    const float* X    = (const float*)d_in[0];
    const int*   mask = (const int*)  d_in[1];
    const int*   pos  = (const int*)  d_in[2];
    const float* Wq   = (const float*)d_in[3];
    const float* Wk   = (const float*)d_in[4];
    const float* Wv   = (const float*)d_in[5];
    const float* Wo   = (const float*)d_in[6];
    float* out = (float*)d_out;

    float *q, *k, *v, *attn;
    cudaGetSymbolAddress((void**)&q,    g_q);
    cudaGetSymbolAddress((void**)&k,    g_k);
    cudaGetSymbolAddress((void**)&v,    g_v);
    cudaGetSymbolAddress((void**)&attn, g_attn);

    cudaFuncSetAttribute(mma_gemm, cudaFuncAttributeMaxDynamicSharedMemorySize, GEMM_SMEM_BYTES);
    cudaFuncSetAttribute(mma_gemm_qkv, cudaFuncAttributeMaxDynamicSharedMemorySize, GEMM_SMEM_BYTES);
    cudaFuncSetAttribute(fa_mma_kernel, cudaFuncAttributeMaxDynamicSharedMemorySize, FA2_SMEM_BYTES);

    // Fused QKV projections + RoPE (24 column tiles: 16 Q, 4 K, 4 V)
    mma_gemm_qkv<<<dim3(24, TOK / GBM), 512, GEMM_SMEM_BYTES>>>(X, Wq, Wk, Wv, q, k, v, pos);

    // Tensor-core flash attention
    fa_mma_kernel<<<dim3(SEQ / 128, NH, BATCH), 256, FA2_SMEM_BYTES>>>(q, k, v, mask, attn);

    // Output projection
    mma_gemm<<<dim3(DM / GBN, TOK / GBM), 512, GEMM_SMEM_BYTES>>>(attn, Wo, out, DM, DM);
}